// round 2
// baseline (speedup 1.0000x reference)
#include <cuda_runtime.h>
#include <math.h>
#include <stdint.h>

#define DIMV 768
#define NLV 12
#define DSV 16
#define DIV 1536
#define TOKV 8192      // 32 batches * 256 tokens
#define LV 256
#define GSV 5

// ---------------- scratch (static device globals; no allocation allowed) ----
__device__ float g_tmp[TOKV * DIMV];                 // im2col buffer / KAN accumulator
__device__ float g_h[TOKV * DIMV];                   // running hidden state
__device__ float g_xr[(size_t)TOKV * 2 * DIV];       // in_proj output (x1|res)
__device__ float g_x1[(size_t)TOKV * DIV];           // post conv+silu
__device__ float g_yg[(size_t)TOKV * DIV];           // gated y before out_proj
__device__ float g_dt[TOKV * DSV];                   // raw dt (pre-softplus, bias added)
__device__ float g_Bpm[TOKV * DSV];                  // B projection
__device__ float g_Ad[TOKV * DSV];
__device__ float g_Bd[TOKV * DSV];
__device__ float g_ys[TOKV * DSV];
__device__ float g_basis[(size_t)TOKV * DIMV * GSV]; // KAN spline basis (K=3840)
__device__ float g_wkan[(size_t)DIMV * DIMV * GSV];  // repacked coeff (768 x 3840)

// ---------------- generic SGEMM:  C[M,N] = A[M,K] @ W[N,K]^T  ---------------
// A, W row-major with K contiguous. M % 128 == 0, K % 16 == 0 assumed.
// N may be small (guarded).
#define BM 128
#define BN 128
#define BK 16
#define TM 8
#define TN 8

template<bool BIAS, bool ACC>
__global__ __launch_bounds__(256)
void sgemm_nt(const float* __restrict__ A, const float* __restrict__ W,
              const float* __restrict__ bias, float* __restrict__ C,
              int M, int N, int K)
{
    __shared__ float As[BK][BM + 4];
    __shared__ float Ws[BK][BN + 4];

    const int bn = blockIdx.x, bm = blockIdx.y;
    const int tid = threadIdx.x;
    const int tx = tid & 15, ty = tid >> 4;
    const int row0 = bm * BM, col0 = bn * BN;

    const int lr = tid >> 2;        // 0..63
    const int lc = tid & 3;         // float4 index within BK

    float acc[TM][TN];
#pragma unroll
    for (int i = 0; i < TM; i++)
#pragma unroll
        for (int j = 0; j < TN; j++) acc[i][j] = 0.f;

    for (int kt = 0; kt < K; kt += BK) {
#pragma unroll
        for (int it = 0; it < 2; it++) {
            int r = lr + it * 64;
            float4 v = *reinterpret_cast<const float4*>(
                A + (size_t)(row0 + r) * K + kt + lc * 4);
            As[lc * 4 + 0][r] = v.x; As[lc * 4 + 1][r] = v.y;
            As[lc * 4 + 2][r] = v.z; As[lc * 4 + 3][r] = v.w;
        }
#pragma unroll
        for (int it = 0; it < 2; it++) {
            int r = lr + it * 64;
            int gcol = col0 + r;
            float4 v = make_float4(0.f, 0.f, 0.f, 0.f);
            if (gcol < N)
                v = *reinterpret_cast<const float4*>(
                    W + (size_t)gcol * K + kt + lc * 4);
            Ws[lc * 4 + 0][r] = v.x; Ws[lc * 4 + 1][r] = v.y;
            Ws[lc * 4 + 2][r] = v.z; Ws[lc * 4 + 3][r] = v.w;
        }
        __syncthreads();

#pragma unroll
        for (int k = 0; k < BK; k++) {
            float ra[TM], rb[TN];
#pragma unroll
            for (int i = 0; i < TM; i++) ra[i] = As[k][ty * TM + i];
#pragma unroll
            for (int j = 0; j < TN; j++) rb[j] = Ws[k][tx * TN + j];
#pragma unroll
            for (int i = 0; i < TM; i++)
#pragma unroll
                for (int j = 0; j < TN; j++) acc[i][j] = fmaf(ra[i], rb[j], acc[i][j]);
        }
        __syncthreads();
    }

#pragma unroll
    for (int i = 0; i < TM; i++) {
        size_t grow = (size_t)(row0 + ty * TM + i);
#pragma unroll
        for (int j = 0; j < TN; j++) {
            int gcol = col0 + tx * TN + j;
            if (gcol < N) {
                float v = acc[i][j];
                if (BIAS) v += bias[gcol];
                if (ACC)  v += C[grow * N + gcol];
                C[grow * N + gcol] = v;
            }
        }
    }
}

// ---------------- elementwise / small kernels ------------------------------

__global__ void im2col_k(const float* __restrict__ x)
{
    int idx = blockIdx.x * blockDim.x + threadIdx.x;
    if (idx >= TOKV * DIMV) return;
    int col = idx % DIMV;
    int row = idx / DIMV;
    int b = row >> 8, t = row & 255;
    int py = t >> 4, px = t & 15;
    int c = col >> 8, rj = col & 255;
    int r = rj >> 4, s = rj & 15;
    g_tmp[idx] = x[(((size_t)(b * 3 + c) * 256) + py * 16 + r) * 256 + px * 16 + s];
}

__global__ void addpos_k(const float* __restrict__ pos)
{
    int idx = blockIdx.x * blockDim.x + threadIdx.x;
    if (idx >= TOKV * DIMV) return;
    int d = idx % DIMV;
    int row = idx / DIMV;
    g_h[idx] += pos[(row & 255) * DIMV + d];
}

// depthwise causal conv (kernel 4) + silu; cw/cb pre-offset per layer
__global__ void conv_silu_k(const float* __restrict__ cw, const float* __restrict__ cb)
{
    int idx = blockIdx.x * blockDim.x + threadIdx.x;
    if (idx >= TOKV * DIV) return;
    int c = idx % DIV;
    int row = idx / DIV;
    int l = row & 255;
    float a = cb[c];
    const float* cwc = cw + c * 4;
#pragma unroll
    for (int k = 0; k < 4; k++) {
        int l2 = l - 3 + k;
        if (l2 >= 0)
            a = fmaf(g_xr[(size_t)(row - 3 + k) * (2 * DIV) + c], cwc[k], a);
    }
    g_x1[idx] = a / (1.f + expf(-a));   // silu
}

// per-row (warp): u = mean(x1[:96]); Ad = exp(-exp(alog)*softplus(dt)); Bd = dt*Bp*u
__global__ void adbd_k(const float* __restrict__ alog)
{
    int g = blockIdx.x * blockDim.x + threadIdx.x;
    int warp = g >> 5;
    int lane = g & 31;
    if (warp >= TOKV) return;
    float s = 0.f;
    for (int d = lane; d < 96; d += 32) s += g_x1[(size_t)warp * DIV + d];
#pragma unroll
    for (int o = 16; o; o >>= 1) s += __shfl_xor_sync(0xffffffffu, s, o);
    float u = s * (1.f / 96.f);
    if (lane < DSV) {
        int n = lane;
        float raw = g_dt[warp * DSV + n];
        float dtv = fmaxf(raw, 0.f) + log1pf(expf(-fabsf(raw)));  // softplus
        float Aa = -expf(alog[n]);
        g_Ad[warp * DSV + n] = expf(Aa * dtv);
        g_Bd[warp * DSV + n] = dtv * g_Bpm[warp * DSV + n] * u;
    }
}

__global__ void scan_k()
{
    int tid = blockIdx.x * blockDim.x + threadIdx.x;
    if (tid >= 32 * DSV) return;
    int b = tid >> 4, n = tid & 15;
    float s = 0.f;
    size_t base = (size_t)b * LV * DSV + n;
    for (int l = 0; l < LV; l++) {
        size_t idx = base + (size_t)l * DSV;
        s = fmaf(s, g_Ad[idx], g_Bd[idx]);
        g_ys[idx] = s;
    }
}

__global__ void yg_k(const float* __restrict__ Dp)
{
    int idx = blockIdx.x * blockDim.x + threadIdx.x;
    if (idx >= TOKV * DIV) return;
    int c = idx % DIV;
    int row = idx / DIV;
    float y = g_ys[row * DSV + c / 96] + g_x1[idx] * Dp[c];
    float r = g_xr[(size_t)row * (2 * DIV) + DIV + c];
    g_yg[idx] = y * (r / (1.f + expf(-r)));
}

// repack kan_coeff[j] (768,768,8) -> (768, 768*5) dense K-major
__global__ void repack_k(const float* __restrict__ coeff)
{
    int idx = blockIdx.x * blockDim.x + threadIdx.x;
    const int TOTAL = DIMV * DIMV * GSV;
    if (idx >= TOTAL) return;
    int o = idx / (DIMV * GSV);
    int r2 = idx % (DIMV * GSV);
    int ii = r2 / GSV;
    int k = r2 % GSV;
    g_wkan[idx] = coeff[((size_t)o * DIMV + ii) * 8 + k];
}

__global__ void basis_k()
{
    int idx = blockIdx.x * blockDim.x + threadIdx.x;
    if (idx >= TOKV * DIMV) return;
    float xv = g_h[idx];
    size_t base = (size_t)idx * GSV;
    const float inv = 1.f / (0.4f + 1e-8f);
#pragma unroll
    for (int k = 0; k < GSV; k++) {
        float gk = -1.f + 0.4f * (float)k;
        float xs = (xv - gk) * inv;
        g_basis[base + k] = (xs >= 0.f && xs < 1.f) ? xs : 0.f;
    }
}

__global__ void resadd_k()
{
    int idx = blockIdx.x * blockDim.x + threadIdx.x;
    if (idx >= TOKV * DIMV) return;
    g_h[idx] = g_tmp[idx] + g_h[idx];
}

__global__ void ln_k(const float* __restrict__ nw, const float* __restrict__ nb,
                     float* __restrict__ out)
{
    __shared__ float sh[DIMV];
    __shared__ float sbuf[8];
    int row = blockIdx.x;
    int tid = threadIdx.x;   // 256 threads
    int lane = tid & 31, w = tid >> 5;

    float s = 0.f;
    for (int d = tid; d < DIMV; d += 256) {
        float v = g_h[(size_t)row * DIMV + d];
        sh[d] = v; s += v;
    }
#pragma unroll
    for (int o = 16; o; o >>= 1) s += __shfl_xor_sync(0xffffffffu, s, o);
    if (lane == 0) sbuf[w] = s;
    __syncthreads();
    if (w == 0) {
        float t = (lane < 8) ? sbuf[lane] : 0.f;
#pragma unroll
        for (int o = 4; o; o >>= 1) t += __shfl_xor_sync(0xffffffffu, t, o);
        if (lane == 0) sbuf[0] = t;
    }
    __syncthreads();
    float mu = sbuf[0] * (1.f / DIMV);
    __syncthreads();

    float s2 = 0.f;
    for (int d = tid; d < DIMV; d += 256) {
        float dv = sh[d] - mu;
        s2 += dv * dv;
    }
#pragma unroll
    for (int o = 16; o; o >>= 1) s2 += __shfl_xor_sync(0xffffffffu, s2, o);
    if (lane == 0) sbuf[w] = s2;
    __syncthreads();
    if (w == 0) {
        float t = (lane < 8) ? sbuf[lane] : 0.f;
#pragma unroll
        for (int o = 4; o; o >>= 1) t += __shfl_xor_sync(0xffffffffu, t, o);
        if (lane == 0) sbuf[0] = t;
    }
    __syncthreads();
    float var = sbuf[0] * (1.f / DIMV);
    float inv = rsqrtf(var + 1e-5f);
    for (int d = tid; d < DIMV; d += 256) {
        out[(size_t)row * DIMV + d] = (sh[d] - mu) * inv * nw[d] + nb[d];
    }
}

// ---------------- host orchestration ---------------------------------------

extern "C" void kernel_launch(void* const* d_in, const int* in_sizes, int n_in,
                              void* d_out, int out_size)
{
    const float* x       = (const float*)d_in[0];
    const float* patch_w = (const float*)d_in[1];
    const float* patch_b = (const float*)d_in[2];
    const float* pos     = (const float*)d_in[3];
    const float* in_w    = (const float*)d_in[4];
    const float* conv_w  = (const float*)d_in[5];
    const float* conv_b  = (const float*)d_in[6];
    const float* xpw     = (const float*)d_in[7];
    const float* dtw     = (const float*)d_in[8];
    const float* dtb     = (const float*)d_in[9];
    const float* alog    = (const float*)d_in[10];
    const float* Dp      = (const float*)d_in[11];
    const float* ow      = (const float*)d_in[12];
    const float* kbw     = (const float*)d_in[13];
    const float* kco     = (const float*)d_in[14];
    const float* kbi     = (const float*)d_in[15];
    const float* nw      = (const float*)d_in[16];
    const float* nb      = (const float*)d_in[17];
    float* out = (float*)d_out;

    float *p_tmp, *p_h, *p_xr, *p_x1, *p_yg, *p_dt, *p_Bp, *p_basis, *p_wkan;
    cudaGetSymbolAddress((void**)&p_tmp,   g_tmp);
    cudaGetSymbolAddress((void**)&p_h,     g_h);
    cudaGetSymbolAddress((void**)&p_xr,    g_xr);
    cudaGetSymbolAddress((void**)&p_x1,    g_x1);
    cudaGetSymbolAddress((void**)&p_yg,    g_yg);
    cudaGetSymbolAddress((void**)&p_dt,    g_dt);
    cudaGetSymbolAddress((void**)&p_Bp,    g_Bpm);
    cudaGetSymbolAddress((void**)&p_basis, g_basis);
    cudaGetSymbolAddress((void**)&p_wkan,  g_wkan);

    const int T = 256;
    const int MB = TOKV / BM;   // 64 row-blocks

    // ---- patch embed ----
    im2col_k<<<(TOKV * DIMV + T - 1) / T, T>>>(x);
    sgemm_nt<true, false><<<dim3(DIMV / BN, MB), T>>>(p_tmp, patch_w, patch_b, p_h,
                                                      TOKV, DIMV, DIMV);
    addpos_k<<<(TOKV * DIMV + T - 1) / T, T>>>(pos);

    for (int i = 0; i < NLV; i++) {
        // in_proj: (8192,768) @ (3072,768)^T
        sgemm_nt<false, false><<<dim3(2 * DIV / BN, MB), T>>>(
            p_h, in_w + (size_t)i * 2 * DIV * DIMV, nullptr, p_xr,
            TOKV, 2 * DIV, DIMV);
        conv_silu_k<<<(TOKV * DIV + T - 1) / T, T>>>(
            conv_w + (size_t)i * DIV * 4, conv_b + (size_t)i * DIV);
        // dt raw (+bias), N=16
        sgemm_nt<true, false><<<dim3(1, MB), T>>>(
            p_x1, dtw + (size_t)i * DSV * DIV, dtb + (size_t)i * DSV, p_dt,
            TOKV, DSV, DIV);
        // Bp = x1 @ xpw[16:32]^T, N=16
        sgemm_nt<false, false><<<dim3(1, MB), T>>>(
            p_x1, xpw + (size_t)i * 2 * DSV * DIV + (size_t)DSV * DIV, nullptr, p_Bp,
            TOKV, DSV, DIV);
        adbd_k<<<(TOKV * 32 + T - 1) / T, T>>>(alog + (size_t)i * DSV);
        scan_k<<<2, 256>>>();
        yg_k<<<(TOKV * DIV + T - 1) / T, T>>>(Dp + (size_t)i * DIV);
        // out_proj
        sgemm_nt<false, false><<<dim3(DIMV / BN, MB), T>>>(
            p_yg, ow + (size_t)i * DIMV * DIV, nullptr, p_h,
            TOKV, DIMV, DIV);

        if (i % 3 == 2) {
            int j = i / 3;
            repack_k<<<(DIMV * DIMV * GSV + T - 1) / T, T>>>(
                kco + (size_t)j * DIMV * DIMV * 8);
            basis_k<<<(TOKV * DIMV + T - 1) / T, T>>>();
            sgemm_nt<true, false><<<dim3(DIMV / BN, MB), T>>>(
                p_h, kbw + (size_t)j * DIMV * DIMV, kbi + (size_t)j * DIMV, p_tmp,
                TOKV, DIMV, DIMV);
            sgemm_nt<false, true><<<dim3(DIMV / BN, MB), T>>>(
                p_basis, p_wkan, nullptr, p_tmp,
                TOKV, DIMV, DIMV * GSV);
            resadd_k<<<(TOKV * DIMV + T - 1) / T, T>>>();
        }
    }

    ln_k<<<TOKV, 256>>>(nw, nb, out);
}

// round 3
// speedup vs baseline: 2.1063x; 2.1063x over previous
#include <cuda_runtime.h>
#include <math.h>
#include <stdint.h>

#define DIMV 768
#define NLV 12
#define DSV 16
#define DIV 1536
#define TOKV 8192      // 32 batches * 256 tokens
#define LV 256
#define GSV 5

// ---------------- scratch (static device globals; no allocation allowed) ----
__device__ float g_tmp[TOKV * DIMV];                 // im2col buffer / KAN accumulator
__device__ float g_h[TOKV * DIMV];                   // running hidden state
__device__ float g_xr[(size_t)TOKV * 2 * DIV];       // in_proj output (x1|res)
__device__ float g_x1[(size_t)TOKV * DIV];           // post conv+silu
__device__ float g_yg[(size_t)TOKV * DIV];           // gated y before out_proj
__device__ float g_Ad[TOKV * DSV];
__device__ float g_Bd[TOKV * DSV];
__device__ float g_ys[TOKV * DSV];
__device__ float g_basis[(size_t)TOKV * DIMV * GSV]; // KAN spline basis (K=3840)
__device__ float g_wkan[(size_t)DIMV * DIMV * GSV];  // repacked coeff (768 x 3840)

// ---------------- SGEMM:  C[M,N] = A[M,K] @ W[N,K]^T  ----------------------
// Double-buffered smem, register-staged global prefetch, one sync per k-tile.
// Requires M%128==0, N%128==0, K%16==0.
#define BM 128
#define BN 128
#define BK 16

template<bool BIAS, bool ACC>
__global__ __launch_bounds__(256, 2)
void sgemm_nt(const float* __restrict__ A, const float* __restrict__ W,
              const float* __restrict__ bias, float* __restrict__ C,
              int M, int N, int K)
{
    __shared__ float As[2][BK][BM + 4];
    __shared__ float Ws[2][BK][BN + 4];

    const int tid = threadIdx.x;
    const int tx = tid & 15, ty = tid >> 4;
    const int row0 = blockIdx.y * BM, col0 = blockIdx.x * BN;

    const int lr = tid >> 2;          // 0..63
    const int lc = (tid & 3) * 4;     // 0,4,8,12

    const float* Ap0 = A + (size_t)(row0 + lr) * K + lc;
    const float* Ap1 = Ap0 + (size_t)64 * K;
    const float* Wp0 = W + (size_t)(col0 + lr) * K + lc;
    const float* Wp1 = Wp0 + (size_t)64 * K;

    float4 a0, a1, w0, w1;
    a0 = *(const float4*)Ap0;
    a1 = *(const float4*)Ap1;
    w0 = *(const float4*)Wp0;
    w1 = *(const float4*)Wp1;

    // store stage 0
    {
        As[0][lc + 0][lr] = a0.x; As[0][lc + 1][lr] = a0.y;
        As[0][lc + 2][lr] = a0.z; As[0][lc + 3][lr] = a0.w;
        As[0][lc + 0][lr + 64] = a1.x; As[0][lc + 1][lr + 64] = a1.y;
        As[0][lc + 2][lr + 64] = a1.z; As[0][lc + 3][lr + 64] = a1.w;
        Ws[0][lc + 0][lr] = w0.x; Ws[0][lc + 1][lr] = w0.y;
        Ws[0][lc + 2][lr] = w0.z; Ws[0][lc + 3][lr] = w0.w;
        Ws[0][lc + 0][lr + 64] = w1.x; Ws[0][lc + 1][lr + 64] = w1.y;
        Ws[0][lc + 2][lr + 64] = w1.z; Ws[0][lc + 3][lr + 64] = w1.w;
    }
    __syncthreads();

    float acc[8][8];
#pragma unroll
    for (int i = 0; i < 8; i++)
#pragma unroll
        for (int j = 0; j < 8; j++) acc[i][j] = 0.f;

    const int nk = K / BK;
    int buf = 0;

    for (int kt = 0; kt < nk; kt++) {
        const bool more = (kt + 1 < nk);
        if (more) {
            int off = (kt + 1) * BK;
            a0 = *(const float4*)(Ap0 + off);
            a1 = *(const float4*)(Ap1 + off);
            w0 = *(const float4*)(Wp0 + off);
            w1 = *(const float4*)(Wp1 + off);
        }
#pragma unroll
        for (int k = 0; k < BK; k++) {
            float ra[8], rb[8];
            *(float4*)&ra[0] = *(const float4*)&As[buf][k][ty * 4];
            *(float4*)&ra[4] = *(const float4*)&As[buf][k][64 + ty * 4];
            *(float4*)&rb[0] = *(const float4*)&Ws[buf][k][tx * 4];
            *(float4*)&rb[4] = *(const float4*)&Ws[buf][k][64 + tx * 4];
#pragma unroll
            for (int i = 0; i < 8; i++)
#pragma unroll
                for (int j = 0; j < 8; j++)
                    acc[i][j] = fmaf(ra[i], rb[j], acc[i][j]);
        }
        if (more) {
            int nb = buf ^ 1;
            As[nb][lc + 0][lr] = a0.x; As[nb][lc + 1][lr] = a0.y;
            As[nb][lc + 2][lr] = a0.z; As[nb][lc + 3][lr] = a0.w;
            As[nb][lc + 0][lr + 64] = a1.x; As[nb][lc + 1][lr + 64] = a1.y;
            As[nb][lc + 2][lr + 64] = a1.z; As[nb][lc + 3][lr + 64] = a1.w;
            Ws[nb][lc + 0][lr] = w0.x; Ws[nb][lc + 1][lr] = w0.y;
            Ws[nb][lc + 2][lr] = w0.z; Ws[nb][lc + 3][lr] = w0.w;
            Ws[nb][lc + 0][lr + 64] = w1.x; Ws[nb][lc + 1][lr + 64] = w1.y;
            Ws[nb][lc + 2][lr + 64] = w1.z; Ws[nb][lc + 3][lr + 64] = w1.w;
            __syncthreads();
            buf = nb;
        }
    }

    // epilogue: rows {ty*4+i, 64+ty*4+i}, cols {tx*4+j, 64+tx*4+j}
    const int cA = col0 + tx * 4;
    const int cB = col0 + 64 + tx * 4;
    float4 bA, bB;
    if (BIAS) {
        bA = *(const float4*)(bias + cA);
        bB = *(const float4*)(bias + cB);
    }
#pragma unroll
    for (int hr = 0; hr < 2; hr++) {
#pragma unroll
        for (int i = 0; i < 4; i++) {
            size_t r = (size_t)(row0 + hr * 64 + ty * 4 + i);
            float4 v0 = make_float4(acc[hr * 4 + i][0], acc[hr * 4 + i][1],
                                    acc[hr * 4 + i][2], acc[hr * 4 + i][3]);
            float4 v1 = make_float4(acc[hr * 4 + i][4], acc[hr * 4 + i][5],
                                    acc[hr * 4 + i][6], acc[hr * 4 + i][7]);
            if (BIAS) {
                v0.x += bA.x; v0.y += bA.y; v0.z += bA.z; v0.w += bA.w;
                v1.x += bB.x; v1.y += bB.y; v1.z += bB.z; v1.w += bB.w;
            }
            float* p0 = C + r * N + cA;
            float* p1 = C + r * N + cB;
            if (ACC) {
                float4 o0 = *(const float4*)p0, o1 = *(const float4*)p1;
                v0.x += o0.x; v0.y += o0.y; v0.z += o0.z; v0.w += o0.w;
                v1.x += o1.x; v1.y += o1.y; v1.z += o1.z; v1.w += o1.w;
            }
            *(float4*)p0 = v0;
            *(float4*)p1 = v1;
        }
    }
}

// ---------------- fused dt + Bp projection + softplus/Ad/Bd ----------------
// Each block: 64 rows x 32 cols (cols 0..15 = dt, 16..31 = Bp), K = 1536.
// Also computes u = mean(x1[:,:96]) and writes g_Ad / g_Bd directly.
__global__ __launch_bounds__(256)
void dtbp_k(const float* __restrict__ dtw, const float* __restrict__ dtb,
            const float* __restrict__ xpw, const float* __restrict__ alog)
{
    __shared__ float Xs[64][36];
    __shared__ float Ws2[32][33];

    const int tid = threadIdx.x;
    const int lane = tid & 31;
    const int wid = tid >> 5;          // 0..7  (row group)
    const int row0 = blockIdx.x * 64;

    const int xrow = tid >> 3;          // 0..31
    const int xk4  = (tid & 7) * 4;

    float acc[8];
#pragma unroll
    for (int r = 0; r < 8; r++) acc[r] = 0.f;

    const float* wsrc = (xrow < 16)
        ? (dtw + (size_t)xrow * DIV)
        : (xpw + (size_t)xrow * DIV);   // rows 16..31 of xpw == Bp rows (DS + c)

    for (int kt = 0; kt < DIV; kt += 32) {
        // load x1 tile: 64 rows x 32 k
        float4 xa = *(const float4*)(g_x1 + (size_t)(row0 + xrow) * DIV + kt + xk4);
        float4 xb = *(const float4*)(g_x1 + (size_t)(row0 + 32 + xrow) * DIV + kt + xk4);
        *(float4*)&Xs[xrow][xk4] = xa;
        *(float4*)&Xs[32 + xrow][xk4] = xb;
        // load combined weight tile: 32 rows x 32 k (scalar stores, padded 33)
        float4 wv = *(const float4*)(wsrc + kt + xk4);
        Ws2[xrow][xk4 + 0] = wv.x; Ws2[xrow][xk4 + 1] = wv.y;
        Ws2[xrow][xk4 + 2] = wv.z; Ws2[xrow][xk4 + 3] = wv.w;
        __syncthreads();

#pragma unroll
        for (int kk = 0; kk < 32; kk++) {
            float w = Ws2[lane][kk];
#pragma unroll
            for (int r = 0; r < 8; r++)
                acc[r] = fmaf(Xs[wid * 8 + r][kk], w, acc[r]);
        }
        __syncthreads();
    }

    // epilogue: per row compute u, then Ad/Bd
    float dtb_v = (lane < DSV) ? dtb[lane] : 0.f;
    float negA  = (lane < DSV) ? -expf(alog[lane]) : 0.f;

#pragma unroll
    for (int r = 0; r < 8; r++) {
        int row = row0 + wid * 8 + r;
        const float* xr = g_x1 + (size_t)row * DIV;
        float s = xr[lane] + xr[lane + 32] + xr[lane + 64];
#pragma unroll
        for (int o = 16; o; o >>= 1) s += __shfl_xor_sync(0xffffffffu, s, o);
        float u = s * (1.f / 96.f);
        float bp = __shfl_sync(0xffffffffu, acc[r], (lane & 15) + 16);
        if (lane < DSV) {
            float raw = acc[r] + dtb_v;
            float dtv = fmaxf(raw, 0.f) + log1pf(expf(-fabsf(raw)));  // softplus
            g_Ad[row * DSV + lane] = expf(negA * dtv);
            g_Bd[row * DSV + lane] = dtv * bp * u;
        }
    }
}

// ---------------- elementwise / small kernels ------------------------------

__global__ void im2col_k(const float* __restrict__ x)
{
    int idx = blockIdx.x * blockDim.x + threadIdx.x;
    if (idx >= TOKV * DIMV) return;
    int col = idx % DIMV;
    int row = idx / DIMV;
    int b = row >> 8, t = row & 255;
    int py = t >> 4, px = t & 15;
    int c = col >> 8, rj = col & 255;
    int r = rj >> 4, s = rj & 15;
    g_tmp[idx] = x[(((size_t)(b * 3 + c) * 256) + py * 16 + r) * 256 + px * 16 + s];
}

__global__ void addpos_k(const float* __restrict__ pos)
{
    int idx = blockIdx.x * blockDim.x + threadIdx.x;
    if (idx >= TOKV * DIMV) return;
    int d = idx % DIMV;
    int row = idx / DIMV;
    g_h[idx] += pos[(row & 255) * DIMV + d];
}

// depthwise causal conv (kernel 4) + silu; cw/cb pre-offset per layer
__global__ void conv_silu_k(const float* __restrict__ cw, const float* __restrict__ cb)
{
    int idx = blockIdx.x * blockDim.x + threadIdx.x;
    if (idx >= TOKV * DIV) return;
    int c = idx % DIV;
    int row = idx / DIV;
    int l = row & 255;
    float a = cb[c];
    const float* cwc = cw + c * 4;
#pragma unroll
    for (int k = 0; k < 4; k++) {
        int l2 = l - 3 + k;
        if (l2 >= 0)
            a = fmaf(g_xr[(size_t)(row - 3 + k) * (2 * DIV) + c], cwc[k], a);
    }
    g_x1[idx] = a / (1.f + expf(-a));   // silu
}

__global__ void scan_k()
{
    int tid = blockIdx.x * blockDim.x + threadIdx.x;
    if (tid >= 32 * DSV) return;
    int b = tid >> 4, n = tid & 15;
    float s = 0.f;
    size_t base = (size_t)b * LV * DSV + n;
    for (int l = 0; l < LV; l++) {
        size_t idx = base + (size_t)l * DSV;
        s = fmaf(s, g_Ad[idx], g_Bd[idx]);
        g_ys[idx] = s;
    }
}

__global__ void yg_k(const float* __restrict__ Dp)
{
    int idx = blockIdx.x * blockDim.x + threadIdx.x;
    if (idx >= TOKV * DIV) return;
    int c = idx % DIV;
    int row = idx / DIV;
    float y = g_ys[row * DSV + c / 96] + g_x1[idx] * Dp[c];
    float r = g_xr[(size_t)row * (2 * DIV) + DIV + c];
    g_yg[idx] = y * (r / (1.f + expf(-r)));
}

// repack kan_coeff[j] (768,768,8) -> (768, 768*5) dense K-major
__global__ void repack_k(const float* __restrict__ coeff)
{
    int idx = blockIdx.x * blockDim.x + threadIdx.x;
    const int TOTAL = DIMV * DIMV * GSV;
    if (idx >= TOTAL) return;
    int o = idx / (DIMV * GSV);
    int r2 = idx % (DIMV * GSV);
    int ii = r2 / GSV;
    int k = r2 % GSV;
    g_wkan[idx] = coeff[((size_t)o * DIMV + ii) * 8 + k];
}

__global__ void basis_k()
{
    int idx = blockIdx.x * blockDim.x + threadIdx.x;
    if (idx >= TOKV * DIMV) return;
    float xv = g_h[idx];
    size_t base = (size_t)idx * GSV;
    const float inv = 1.f / (0.4f + 1e-8f);
#pragma unroll
    for (int k = 0; k < GSV; k++) {
        float gk = -1.f + 0.4f * (float)k;
        float xs = (xv - gk) * inv;
        g_basis[base + k] = (xs >= 0.f && xs < 1.f) ? xs : 0.f;
    }
}

__global__ void resadd_k()
{
    int idx = blockIdx.x * blockDim.x + threadIdx.x;
    if (idx >= TOKV * DIMV) return;
    g_h[idx] = g_tmp[idx] + g_h[idx];
}

__global__ void ln_k(const float* __restrict__ nw, const float* __restrict__ nb,
                     float* __restrict__ out)
{
    __shared__ float sh[DIMV];
    __shared__ float sbuf[8];
    int row = blockIdx.x;
    int tid = threadIdx.x;   // 256 threads
    int lane = tid & 31, w = tid >> 5;

    float s = 0.f;
    for (int d = tid; d < DIMV; d += 256) {
        float v = g_h[(size_t)row * DIMV + d];
        sh[d] = v; s += v;
    }
#pragma unroll
    for (int o = 16; o; o >>= 1) s += __shfl_xor_sync(0xffffffffu, s, o);
    if (lane == 0) sbuf[w] = s;
    __syncthreads();
    if (w == 0) {
        float t = (lane < 8) ? sbuf[lane] : 0.f;
#pragma unroll
        for (int o = 4; o; o >>= 1) t += __shfl_xor_sync(0xffffffffu, t, o);
        if (lane == 0) sbuf[0] = t;
    }
    __syncthreads();
    float mu = sbuf[0] * (1.f / DIMV);
    __syncthreads();

    float s2 = 0.f;
    for (int d = tid; d < DIMV; d += 256) {
        float dv = sh[d] - mu;
        s2 += dv * dv;
    }
#pragma unroll
    for (int o = 16; o; o >>= 1) s2 += __shfl_xor_sync(0xffffffffu, s2, o);
    if (lane == 0) sbuf[w] = s2;
    __syncthreads();
    if (w == 0) {
        float t = (lane < 8) ? sbuf[lane] : 0.f;
#pragma unroll
        for (int o = 4; o; o >>= 1) t += __shfl_xor_sync(0xffffffffu, t, o);
        if (lane == 0) sbuf[0] = t;
    }
    __syncthreads();
    float var = sbuf[0] * (1.f / DIMV);
    float inv = rsqrtf(var + 1e-5f);
    for (int d = tid; d < DIMV; d += 256) {
        out[(size_t)row * DIMV + d] = (sh[d] - mu) * inv * nw[d] + nb[d];
    }
}

// ---------------- host orchestration ---------------------------------------

extern "C" void kernel_launch(void* const* d_in, const int* in_sizes, int n_in,
                              void* d_out, int out_size)
{
    const float* x       = (const float*)d_in[0];
    const float* patch_w = (const float*)d_in[1];
    const float* patch_b = (const float*)d_in[2];
    const float* pos     = (const float*)d_in[3];
    const float* in_w    = (const float*)d_in[4];
    const float* conv_w  = (const float*)d_in[5];
    const float* conv_b  = (const float*)d_in[6];
    const float* xpw     = (const float*)d_in[7];
    const float* dtw     = (const float*)d_in[8];
    const float* dtb     = (const float*)d_in[9];
    const float* alog    = (const float*)d_in[10];
    const float* Dp      = (const float*)d_in[11];
    const float* ow      = (const float*)d_in[12];
    const float* kbw     = (const float*)d_in[13];
    const float* kco     = (const float*)d_in[14];
    const float* kbi     = (const float*)d_in[15];
    const float* nw      = (const float*)d_in[16];
    const float* nb      = (const float*)d_in[17];
    float* out = (float*)d_out;

    float *p_tmp, *p_h, *p_xr, *p_x1, *p_yg, *p_basis, *p_wkan;
    cudaGetSymbolAddress((void**)&p_tmp,   g_tmp);
    cudaGetSymbolAddress((void**)&p_h,     g_h);
    cudaGetSymbolAddress((void**)&p_xr,    g_xr);
    cudaGetSymbolAddress((void**)&p_x1,    g_x1);
    cudaGetSymbolAddress((void**)&p_yg,    g_yg);
    cudaGetSymbolAddress((void**)&p_basis, g_basis);
    cudaGetSymbolAddress((void**)&p_wkan,  g_wkan);

    const int T = 256;
    const int MB = TOKV / BM;   // 64 row-blocks

    // ---- patch embed ----
    im2col_k<<<(TOKV * DIMV + T - 1) / T, T>>>(x);
    sgemm_nt<true, false><<<dim3(DIMV / BN, MB), T>>>(p_tmp, patch_w, patch_b, p_h,
                                                      TOKV, DIMV, DIMV);
    addpos_k<<<(TOKV * DIMV + T - 1) / T, T>>>(pos);

    for (int i = 0; i < NLV; i++) {
        // in_proj: (8192,768) @ (3072,768)^T
        sgemm_nt<false, false><<<dim3(2 * DIV / BN, MB), T>>>(
            p_h, in_w + (size_t)i * 2 * DIV * DIMV, nullptr, p_xr,
            TOKV, 2 * DIV, DIMV);
        conv_silu_k<<<(TOKV * DIV + T - 1) / T, T>>>(
            conv_w + (size_t)i * DIV * 4, conv_b + (size_t)i * DIV);
        // fused dt + Bp + softplus/Ad/Bd
        dtbp_k<<<TOKV / 64, T>>>(
            dtw + (size_t)i * DSV * DIV, dtb + (size_t)i * DSV,
            xpw + (size_t)i * 2 * DSV * DIV, alog + (size_t)i * DSV);
        scan_k<<<2, 256>>>();
        yg_k<<<(TOKV * DIV + T - 1) / T, T>>>(Dp + (size_t)i * DIV);
        // out_proj
        sgemm_nt<false, false><<<dim3(DIMV / BN, MB), T>>>(
            p_yg, ow + (size_t)i * DIMV * DIV, nullptr, p_h,
            TOKV, DIMV, DIV);

        if (i % 3 == 2) {
            int j = i / 3;
            repack_k<<<(DIMV * DIMV * GSV + T - 1) / T, T>>>(
                kco + (size_t)j * DIMV * DIMV * 8);
            basis_k<<<(TOKV * DIMV + T - 1) / T, T>>>();
            sgemm_nt<true, false><<<dim3(DIMV / BN, MB), T>>>(
                p_h, kbw + (size_t)j * DIMV * DIMV, kbi + (size_t)j * DIMV, p_tmp,
                TOKV, DIMV, DIMV);
            sgemm_nt<false, true><<<dim3(DIMV / BN, MB), T>>>(
                p_basis, p_wkan, nullptr, p_tmp,
                TOKV, DIMV, DIMV * GSV);
            resadd_k<<<(TOKV * DIMV + T - 1) / T, T>>>();
        }
    }

    ln_k<<<TOKV, 256>>>(nw, nb, out);
}

// round 5
// speedup vs baseline: 3.7688x; 1.7893x over previous
#include <cuda_runtime.h>
#include <cuda_bf16.h>
#include <math.h>
#include <stdint.h>

#define DIMV 768
#define NLV 12
#define DSV 16
#define DIV 1536
#define TOKV 8192      // 32 batches * 256 tokens
#define LV 256
#define GSV 5
#define KANK (DIMV * GSV)   // 3840

// ---------------- scratch (static device globals; no allocation allowed) ----
__device__ float g_tmp[TOKV * DIMV];                 // KAN accumulator
__device__ float g_h[TOKV * DIMV];                   // running hidden state
__device__ float g_xr[(size_t)TOKV * 2 * DIV];       // in_proj output (x1|res)
__device__ float g_x1[(size_t)TOKV * DIV];           // post conv+silu
__device__ float g_Ad[TOKV * DSV];
__device__ float g_Bd[TOKV * DSV];
__device__ float g_ys[TOKV * DSV];

// bf16 split activation buffers (largest use: basis 8192 x 3840)
__device__ __nv_bfloat16 g_ah[(size_t)TOKV * KANK];
__device__ __nv_bfloat16 g_al[(size_t)TOKV * KANK];
// bf16 split weights
__device__ __nv_bfloat16 g_wih[(size_t)NLV * 2 * DIV * DIMV];
__device__ __nv_bfloat16 g_wil[(size_t)NLV * 2 * DIV * DIMV];
__device__ __nv_bfloat16 g_woh[(size_t)NLV * DIMV * DIV];
__device__ __nv_bfloat16 g_wol[(size_t)NLV * DIMV * DIV];
__device__ __nv_bfloat16 g_wph[DIMV * DIMV];
__device__ __nv_bfloat16 g_wpl[DIMV * DIMV];
__device__ __nv_bfloat16 g_wkbh[4 * DIMV * DIMV];
__device__ __nv_bfloat16 g_wkbl[4 * DIMV * DIMV];
__device__ __nv_bfloat16 g_wsh[(size_t)4 * DIMV * KANK];
__device__ __nv_bfloat16 g_wsl[(size_t)4 * DIMV * KANK];

// ---------------- PTX helpers ----------------------------------------------
__device__ __forceinline__ uint32_t smem_u32(const void* p) {
    uint32_t a;
    asm("{ .reg .u64 t; cvta.to.shared.u64 t, %1; cvt.u32.u64 %0, t; }"
        : "=r"(a) : "l"(p));
    return a;
}
__device__ __forceinline__ void ldsm4(uint32_t& r0, uint32_t& r1,
                                      uint32_t& r2, uint32_t& r3, uint32_t addr)
{
    asm volatile("ldmatrix.sync.aligned.m8n8.x4.shared.b16 {%0,%1,%2,%3}, [%4];"
                 : "=r"(r0), "=r"(r1), "=r"(r2), "=r"(r3) : "r"(addr));
}
__device__ __forceinline__ void mma16816(float* c, const uint32_t* a, const uint32_t* b)
{
    asm volatile(
        "mma.sync.aligned.m16n8k16.row.col.f32.bf16.bf16.f32 "
        "{%0,%1,%2,%3}, {%4,%5,%6,%7}, {%8,%9}, {%0,%1,%2,%3};"
        : "+f"(c[0]), "+f"(c[1]), "+f"(c[2]), "+f"(c[3])
        : "r"(a[0]), "r"(a[1]), "r"(a[2]), "r"(a[3]), "r"(b[0]), "r"(b[1]));
}
__device__ __forceinline__ void cp16(uint32_t dst, const void* src)
{
    asm volatile("cp.async.cg.shared.global [%0], [%1], 16;"
                 :: "r"(dst), "l"(src) : "memory");
}
__device__ __forceinline__ void cp_commit()
{
    asm volatile("cp.async.commit_group;" ::: "memory");
}
template<int NN> __device__ __forceinline__ void cp_wait()
{
    asm volatile("cp.async.wait_group %0;" :: "n"(NN) : "memory");
}

// ---------------- tensor-core GEMM (HMMA mma.sync) --------------------------
// C[M,N] = (Ah+Al)[M,K] @ (Wh+Wl)[N,K]^T  via 3 bf16 mma terms, fp32 accum.
// M%128==0, N%128==0, K%32==0. 256 threads. Tile rows padded to 80B pitch
// (40 bf16) -> conflict-free ldmatrix without swizzle.
#define TILE_B 10240                 // 128 rows * 80 B
#define STAGE_B (4 * TILE_B)         // Ah | Al | Wh | Wl
#define SMEMT (2 * STAGE_B)          // 81920 B

template<bool BIAS, bool ACC>
__global__ __launch_bounds__(256)
void tgemm(const __nv_bfloat16* __restrict__ Ah, const __nv_bfloat16* __restrict__ Al,
           const __nv_bfloat16* __restrict__ Wh, const __nv_bfloat16* __restrict__ Wl,
           const float* __restrict__ bias, float* __restrict__ C,
           int M, int N, int K)
{
    extern __shared__ char smem[];
    const uint32_t sb0 = smem_u32(smem);
    const int tid = threadIdx.x, lane = tid & 31, wid = tid >> 5;
    const int row0 = blockIdx.y * 128, col0 = blockIdx.x * 128;
    const int wm = wid >> 2, wn = wid & 3;       // 2 x 4 warp grid
    const int rm = wm * 64, cn = wn * 32;

    const __nv_bfloat16* gsrc0 = Ah + (size_t)row0 * K;
    const __nv_bfloat16* gsrc1 = Al + (size_t)row0 * K;
    const __nv_bfloat16* gsrc2 = Wh + (size_t)col0 * K;
    const __nv_bfloat16* gsrc3 = Wl + (size_t)col0 * K;

    const int lrow = tid >> 2;          // 0..63 (two rows per thread via +64)
    const int lch  = tid & 3;           // 16B chunk 0..3

    auto issue = [&](int p, int s) {
        const int k0g = p * 32;
        const uint32_t dstb = sb0 + s * STAGE_B;
        const __nv_bfloat16* gp[4] = { gsrc0, gsrc1, gsrc2, gsrc3 };
#pragma unroll
        for (int t = 0; t < 4; t++) {
#pragma unroll
            for (int i = 0; i < 2; i++) {
                int row = lrow + i * 64;
                const __nv_bfloat16* src = gp[t] + (size_t)row * K + k0g + lch * 8;
                uint32_t dst = dstb + t * TILE_B + row * 80 + lch * 16;
                cp16(dst, src);
            }
        }
        cp_commit();
    };

    float acc[4][4][4];
#pragma unroll
    for (int a = 0; a < 4; a++)
#pragma unroll
        for (int b = 0; b < 4; b++)
#pragma unroll
            for (int q = 0; q < 4; q++) acc[a][b][q] = 0.f;

    // per-lane ldmatrix address components (byte offsets within a tile)
    const uint32_t aRowB = (uint32_t)(rm + (lane & 15)) * 80 + ((lane >> 4) << 4);
    const uint32_t bRowB = (uint32_t)(cn + (lane & 7) + ((lane >> 4) & 1) * 8) * 80
                         + (((lane >> 3) & 1) << 4);

    const int npan = K >> 5;
    issue(0, 0);

    for (int p = 0; p < npan; p++) {
        const bool more = (p + 1 < npan);
        if (more) issue(p + 1, (p + 1) & 1);
        if (more) cp_wait<1>(); else cp_wait<0>();
        __syncthreads();

        const uint32_t sbase = sb0 + (p & 1) * STAGE_B;
#pragma unroll
        for (int ks = 0; ks < 2; ks++) {
            const uint32_t kb = ks * 32;          // 16 bf16 = 32 B
            uint32_t AhF[4][4], AlF[4][4], WhF[4][2], WlF[4][2];
#pragma unroll
            for (int mt = 0; mt < 4; mt++) {
                uint32_t base = sbase + aRowB + mt * (16 * 80) + kb;
                ldsm4(AhF[mt][0], AhF[mt][1], AhF[mt][2], AhF[mt][3], base);
                ldsm4(AlF[mt][0], AlF[mt][1], AlF[mt][2], AlF[mt][3], base + TILE_B);
            }
#pragma unroll
            for (int bt = 0; bt < 2; bt++) {
                uint32_t base = sbase + 2 * TILE_B + bRowB + bt * (16 * 80) + kb;
                uint32_t r0, r1, r2, r3;
                ldsm4(r0, r1, r2, r3, base);
                WhF[bt * 2][0] = r0; WhF[bt * 2][1] = r1;
                WhF[bt * 2 + 1][0] = r2; WhF[bt * 2 + 1][1] = r3;
                ldsm4(r0, r1, r2, r3, base + TILE_B);
                WlF[bt * 2][0] = r0; WlF[bt * 2][1] = r1;
                WlF[bt * 2 + 1][0] = r2; WlF[bt * 2 + 1][1] = r3;
            }
#pragma unroll
            for (int mt = 0; mt < 4; mt++)
#pragma unroll
                for (int nt = 0; nt < 4; nt++) {
                    mma16816(acc[mt][nt], AhF[mt], WhF[nt]);
                    mma16816(acc[mt][nt], AlF[mt], WhF[nt]);
                    mma16816(acc[mt][nt], AhF[mt], WlF[nt]);
                }
        }
        __syncthreads();
    }

    // epilogue
#pragma unroll
    for (int mt = 0; mt < 4; mt++) {
#pragma unroll
        for (int nt = 0; nt < 4; nt++) {
            int r = row0 + rm + mt * 16 + (lane >> 2);
            int c = col0 + cn + nt * 8 + (lane & 3) * 2;
            float bx = 0.f, by = 0.f;
            if (BIAS) { bx = bias[c]; by = bias[c + 1]; }
#pragma unroll
            for (int half = 0; half < 2; half++) {
                float* dst = C + (size_t)(r + half * 8) * N + c;
                float vx = acc[mt][nt][half * 2 + 0] + bx;
                float vy = acc[mt][nt][half * 2 + 1] + by;
                if (ACC) { vx += dst[0]; vy += dst[1]; }
                float2 v = make_float2(vx, vy);
                *reinterpret_cast<float2*>(dst) = v;
            }
        }
    }
}

// ---------------- split / conversion kernels -------------------------------
__device__ __forceinline__ void split_store(float v, __nv_bfloat16* hi,
                                            __nv_bfloat16* lo, size_t idx)
{
    __nv_bfloat16 h = __float2bfloat16(v);
    hi[idx] = h;
    lo[idx] = __float2bfloat16(v - __bfloat162float(h));
}

__global__ void split_k(const float* __restrict__ src, __nv_bfloat16* __restrict__ hi,
                        __nv_bfloat16* __restrict__ lo, int n)
{
    int idx = blockIdx.x * blockDim.x + threadIdx.x;
    if (idx >= n) return;
    split_store(src[idx], hi, lo, idx);
}

// repack kan_coeff (4,768,768,8) -> g_wsh/g_wsl (4,768,3840)
__global__ void repack_split_k(const float* __restrict__ coeff)
{
    int idx = blockIdx.x * blockDim.x + threadIdx.x;
    const int PER = DIMV * KANK;
    if (idx >= 4 * PER) return;
    int j = idx / PER;
    int r = idx % PER;
    int o = r / KANK;
    int r2 = r % KANK;
    int ii = r2 / GSV;
    int k = r2 % GSV;
    float v = coeff[(((size_t)j * DIMV + o) * DIMV + ii) * 8 + k];
    split_store(v, g_wsh, g_wsl, idx);
}

__global__ void im2col_split_k(const float* __restrict__ x)
{
    int idx = blockIdx.x * blockDim.x + threadIdx.x;
    if (idx >= TOKV * DIMV) return;
    int col = idx % DIMV;
    int row = idx / DIMV;
    int b = row >> 8, t = row & 255;
    int py = t >> 4, px = t & 15;
    int c = col >> 8, rj = col & 255;
    int r = rj >> 4, s = rj & 15;
    float v = x[(((size_t)(b * 3 + c) * 256) + py * 16 + r) * 256 + px * 16 + s];
    split_store(v, g_ah, g_al, idx);
}

__global__ void addpos_k(const float* __restrict__ pos)
{
    int idx = blockIdx.x * blockDim.x + threadIdx.x;
    if (idx >= TOKV * DIMV) return;
    int d = idx % DIMV;
    int row = idx / DIMV;
    g_h[idx] += pos[(row & 255) * DIMV + d];
}

// depthwise causal conv (kernel 4) + silu
__global__ void conv_silu_k(const float* __restrict__ cw, const float* __restrict__ cb)
{
    int idx = blockIdx.x * blockDim.x + threadIdx.x;
    if (idx >= TOKV * DIV) return;
    int c = idx % DIV;
    int row = idx / DIV;
    int l = row & 255;
    float a = cb[c];
    const float* cwc = cw + c * 4;
#pragma unroll
    for (int k = 0; k < 4; k++) {
        int l2 = l - 3 + k;
        if (l2 >= 0)
            a = fmaf(g_xr[(size_t)(row - 3 + k) * (2 * DIV) + c], cwc[k], a);
    }
    g_x1[idx] = a / (1.f + expf(-a));
}

// fused dt + Bp projection + softplus/Ad/Bd  (FFMA path; tiny N)
__global__ __launch_bounds__(256)
void dtbp_k(const float* __restrict__ dtw, const float* __restrict__ dtb,
            const float* __restrict__ xpw, const float* __restrict__ alog)
{
    __shared__ float Xs[64][36];
    __shared__ float Ws2[32][33];

    const int tid = threadIdx.x;
    const int lane = tid & 31;
    const int wid = tid >> 5;
    const int row0 = blockIdx.x * 64;

    const int xrow = tid >> 3;
    const int xk4  = (tid & 7) * 4;

    float acc[8];
#pragma unroll
    for (int r = 0; r < 8; r++) acc[r] = 0.f;

    const float* wsrc = (xrow < 16)
        ? (dtw + (size_t)xrow * DIV)
        : (xpw + (size_t)xrow * DIV);

    for (int kt = 0; kt < DIV; kt += 32) {
        float4 xa = *(const float4*)(g_x1 + (size_t)(row0 + xrow) * DIV + kt + xk4);
        float4 xb = *(const float4*)(g_x1 + (size_t)(row0 + 32 + xrow) * DIV + kt + xk4);
        *(float4*)&Xs[xrow][xk4] = xa;
        *(float4*)&Xs[32 + xrow][xk4] = xb;
        float4 wv = *(const float4*)(wsrc + kt + xk4);
        Ws2[xrow][xk4 + 0] = wv.x; Ws2[xrow][xk4 + 1] = wv.y;
        Ws2[xrow][xk4 + 2] = wv.z; Ws2[xrow][xk4 + 3] = wv.w;
        __syncthreads();
#pragma unroll
        for (int kk = 0; kk < 32; kk++) {
            float w = Ws2[lane][kk];
#pragma unroll
            for (int r = 0; r < 8; r++)
                acc[r] = fmaf(Xs[wid * 8 + r][kk], w, acc[r]);
        }
        __syncthreads();
    }

    float dtb_v = (lane < DSV) ? dtb[lane] : 0.f;
    float negA  = (lane < DSV) ? -expf(alog[lane]) : 0.f;

#pragma unroll
    for (int r = 0; r < 8; r++) {
        int row = row0 + wid * 8 + r;
        const float* xr = g_x1 + (size_t)row * DIV;
        float s = xr[lane] + xr[lane + 32] + xr[lane + 64];
#pragma unroll
        for (int o = 16; o; o >>= 1) s += __shfl_xor_sync(0xffffffffu, s, o);
        float u = s * (1.f / 96.f);
        float bp = __shfl_sync(0xffffffffu, acc[r], (lane & 15) + 16);
        if (lane < DSV) {
            float raw = acc[r] + dtb_v;
            float dtv = fmaxf(raw, 0.f) + log1pf(expf(-fabsf(raw)));
            g_Ad[row * DSV + lane] = expf(negA * dtv);
            g_Bd[row * DSV + lane] = dtv * bp * u;
        }
    }
}

__global__ void scan_k()
{
    int tid = blockIdx.x * blockDim.x + threadIdx.x;
    if (tid >= 32 * DSV) return;
    int b = tid >> 4, n = tid & 15;
    float s = 0.f;
    size_t base = (size_t)b * LV * DSV + n;
    for (int l = 0; l < LV; l++) {
        size_t idx = base + (size_t)l * DSV;
        s = fmaf(s, g_Ad[idx], g_Bd[idx]);
        g_ys[idx] = s;
    }
}

// gated y -> bf16 split directly into g_ah/g_al ([8192,1536])
__global__ void yg_split_k(const float* __restrict__ Dp)
{
    int idx = blockIdx.x * blockDim.x + threadIdx.x;
    if (idx >= TOKV * DIV) return;
    int c = idx % DIV;
    int row = idx / DIV;
    float y = g_ys[row * DSV + c / 96] + g_x1[idx] * Dp[c];
    float r = g_xr[(size_t)row * (2 * DIV) + DIV + c];
    float v = y * (r / (1.f + expf(-r)));
    split_store(v, g_ah, g_al, idx);
}

// KAN basis -> bf16 split directly into g_ah/g_al ([8192,3840])
__global__ void basis_split_k()
{
    int idx = blockIdx.x * blockDim.x + threadIdx.x;
    if (idx >= TOKV * DIMV) return;
    float xv = g_h[idx];
    size_t base = (size_t)idx * GSV;
    const float inv = 1.f / (0.4f + 1e-8f);
#pragma unroll
    for (int k = 0; k < GSV; k++) {
        float gk = -1.f + 0.4f * (float)k;
        float xs = (xv - gk) * inv;
        float v = (xs >= 0.f && xs < 1.f) ? xs : 0.f;
        split_store(v, g_ah, g_al, base + k);
    }
}

__global__ void resadd_k()
{
    int idx = blockIdx.x * blockDim.x + threadIdx.x;
    if (idx >= TOKV * DIMV) return;
    g_h[idx] = g_tmp[idx] + g_h[idx];
}

__global__ void ln_k(const float* __restrict__ nw, const float* __restrict__ nb,
                     float* __restrict__ out)
{
    __shared__ float sh[DIMV];
    __shared__ float sbuf[8];
    int row = blockIdx.x;
    int tid = threadIdx.x;
    int lane = tid & 31, w = tid >> 5;

    float s = 0.f;
    for (int d = tid; d < DIMV; d += 256) {
        float v = g_h[(size_t)row * DIMV + d];
        sh[d] = v; s += v;
    }
#pragma unroll
    for (int o = 16; o; o >>= 1) s += __shfl_xor_sync(0xffffffffu, s, o);
    if (lane == 0) sbuf[w] = s;
    __syncthreads();
    if (w == 0) {
        float t = (lane < 8) ? sbuf[lane] : 0.f;
#pragma unroll
        for (int o = 4; o; o >>= 1) t += __shfl_xor_sync(0xffffffffu, t, o);
        if (lane == 0) sbuf[0] = t;
    }
    __syncthreads();
    float mu = sbuf[0] * (1.f / DIMV);
    __syncthreads();

    float s2 = 0.f;
    for (int d = tid; d < DIMV; d += 256) {
        float dv = sh[d] - mu;
        s2 += dv * dv;
    }
#pragma unroll
    for (int o = 16; o; o >>= 1) s2 += __shfl_xor_sync(0xffffffffu, s2, o);
    if (lane == 0) sbuf[w] = s2;
    __syncthreads();
    if (w == 0) {
        float t = (lane < 8) ? sbuf[lane] : 0.f;
#pragma unroll
        for (int o = 4; o; o >>= 1) t += __shfl_xor_sync(0xffffffffu, t, o);
        if (lane == 0) sbuf[0] = t;
    }
    __syncthreads();
    float var = sbuf[0] * (1.f / DIMV);
    float inv = rsqrtf(var + 1e-5f);
    for (int d = tid; d < DIMV; d += 256) {
        out[(size_t)row * DIMV + d] = (sh[d] - mu) * inv * nw[d] + nb[d];
    }
}

// ---------------- host orchestration ---------------------------------------

extern "C" void kernel_launch(void* const* d_in, const int* in_sizes, int n_in,
                              void* d_out, int out_size)
{
    const float* x       = (const float*)d_in[0];
    const float* patch_w = (const float*)d_in[1];
    const float* patch_b = (const float*)d_in[2];
    const float* pos     = (const float*)d_in[3];
    const float* in_w    = (const float*)d_in[4];
    const float* conv_w  = (const float*)d_in[5];
    const float* conv_b  = (const float*)d_in[6];
    const float* xpw     = (const float*)d_in[7];
    const float* dtw     = (const float*)d_in[8];
    const float* dtb     = (const float*)d_in[9];
    const float* alog    = (const float*)d_in[10];
    const float* Dp      = (const float*)d_in[11];
    const float* ow      = (const float*)d_in[12];
    const float* kbw     = (const float*)d_in[13];
    const float* kco     = (const float*)d_in[14];
    const float* kbi     = (const float*)d_in[15];
    const float* nw      = (const float*)d_in[16];
    const float* nb      = (const float*)d_in[17];
    float* out = (float*)d_out;

    cudaFuncSetAttribute(tgemm<false, false>, cudaFuncAttributeMaxDynamicSharedMemorySize, SMEMT);
    cudaFuncSetAttribute(tgemm<true,  false>, cudaFuncAttributeMaxDynamicSharedMemorySize, SMEMT);
    cudaFuncSetAttribute(tgemm<false, true >, cudaFuncAttributeMaxDynamicSharedMemorySize, SMEMT);

    float *p_tmp, *p_h, *p_xr;
    __nv_bfloat16 *p_ah, *p_al, *p_wih, *p_wil, *p_woh, *p_wol;
    __nv_bfloat16 *p_wph, *p_wpl, *p_wkbh, *p_wkbl, *p_wsh, *p_wsl;
    cudaGetSymbolAddress((void**)&p_tmp,  g_tmp);
    cudaGetSymbolAddress((void**)&p_h,    g_h);
    cudaGetSymbolAddress((void**)&p_xr,   g_xr);
    cudaGetSymbolAddress((void**)&p_ah,   g_ah);
    cudaGetSymbolAddress((void**)&p_al,   g_al);
    cudaGetSymbolAddress((void**)&p_wih,  g_wih);
    cudaGetSymbolAddress((void**)&p_wil,  g_wil);
    cudaGetSymbolAddress((void**)&p_woh,  g_woh);
    cudaGetSymbolAddress((void**)&p_wol,  g_wol);
    cudaGetSymbolAddress((void**)&p_wph,  g_wph);
    cudaGetSymbolAddress((void**)&p_wpl,  g_wpl);
    cudaGetSymbolAddress((void**)&p_wkbh, g_wkbh);
    cudaGetSymbolAddress((void**)&p_wkbl, g_wkbl);
    cudaGetSymbolAddress((void**)&p_wsh,  g_wsh);
    cudaGetSymbolAddress((void**)&p_wsl,  g_wsl);

    const int T = 256;
    const int MB = TOKV / 128;   // 64

    // ---- weight conversions (every call; weights are inputs) ----
    {
        int n;
        n = NLV * 2 * DIV * DIMV;
        split_k<<<(n + T - 1) / T, T>>>(in_w, p_wih, p_wil, n);
        n = NLV * DIMV * DIV;
        split_k<<<(n + T - 1) / T, T>>>(ow, p_woh, p_wol, n);
        n = DIMV * DIMV;
        split_k<<<(n + T - 1) / T, T>>>(patch_w, p_wph, p_wpl, n);
        n = 4 * DIMV * DIMV;
        split_k<<<(n + T - 1) / T, T>>>(kbw, p_wkbh, p_wkbl, n);
        n = 4 * DIMV * KANK;
        repack_split_k<<<(n + T - 1) / T, T>>>(kco);
    }

    // ---- patch embed ----
    im2col_split_k<<<(TOKV * DIMV + T - 1) / T, T>>>(x);
    tgemm<true, false><<<dim3(DIMV / 128, MB), T, SMEMT>>>(
        p_ah, p_al, p_wph, p_wpl, patch_b, p_h, TOKV, DIMV, DIMV);
    addpos_k<<<(TOKV * DIMV + T - 1) / T, T>>>(pos);

    for (int i = 0; i < NLV; i++) {
        // split h -> A
        split_k<<<(TOKV * DIMV + T - 1) / T, T>>>(p_h, p_ah, p_al, TOKV * DIMV);
        // in_proj: (8192,768) @ (3072,768)^T -> g_xr
        tgemm<false, false><<<dim3(2 * DIV / 128, MB), T, SMEMT>>>(
            p_ah, p_al, p_wih + (size_t)i * 2 * DIV * DIMV,
            p_wil + (size_t)i * 2 * DIV * DIMV, nullptr, p_xr,
            TOKV, 2 * DIV, DIMV);
        conv_silu_k<<<(TOKV * DIV + T - 1) / T, T>>>(
            conv_w + (size_t)i * DIV * 4, conv_b + (size_t)i * DIV);
        dtbp_k<<<TOKV / 64, T>>>(
            dtw + (size_t)i * DSV * DIV, dtb + (size_t)i * DSV,
            xpw + (size_t)i * 2 * DSV * DIV, alog + (size_t)i * DSV);
        scan_k<<<2, 256>>>();
        yg_split_k<<<(TOKV * DIV + T - 1) / T, T>>>(Dp + (size_t)i * DIV);
        // out_proj: (8192,1536) @ (768,1536)^T -> g_h
        tgemm<false, false><<<dim3(DIMV / 128, MB), T, SMEMT>>>(
            p_ah, p_al, p_woh + (size_t)i * DIMV * DIV,
            p_wol + (size_t)i * DIMV * DIV, nullptr, p_h,
            TOKV, DIMV, DIV);

        if (i % 3 == 2) {
            int j = i / 3;
            // base: split(h) @ kbw^T + kbi -> g_tmp
            split_k<<<(TOKV * DIMV + T - 1) / T, T>>>(p_h, p_ah, p_al, TOKV * DIMV);
            tgemm<true, false><<<dim3(DIMV / 128, MB), T, SMEMT>>>(
                p_ah, p_al, p_wkbh + (size_t)j * DIMV * DIMV,
                p_wkbl + (size_t)j * DIMV * DIMV, kbi + (size_t)j * DIMV, p_tmp,
                TOKV, DIMV, DIMV);
            // spline: basis @ wkan^T  accumulate into g_tmp
            basis_split_k<<<(TOKV * DIMV + T - 1) / T, T>>>();
            tgemm<false, true><<<dim3(DIMV / 128, MB), T, SMEMT>>>(
                p_ah, p_al, p_wsh + (size_t)j * DIMV * KANK,
                p_wsl + (size_t)j * DIMV * KANK, nullptr, p_tmp,
                TOKV, DIMV, KANK);
            resadd_k<<<(TOKV * DIMV + T - 1) / T, T>>>();
        }
    }

    ln_k<<<TOKV, 256>>>(nw, nb, out);
}

// round 6
// speedup vs baseline: 5.2963x; 1.4053x over previous
#include <cuda_runtime.h>
#include <cuda_bf16.h>
#include <math.h>
#include <stdint.h>

#define DIMV 768
#define NLV 12
#define DSV 16
#define DIV 1536
#define TOKV 8192      // 32 batches * 256 tokens
#define LV 256
#define GSV 5
#define KANK (DIMV * GSV)   // 3840

// ---------------- scratch (static device globals; no allocation allowed) ----
__device__ float g_tmp[TOKV * DIMV];                 // im2col / KAN accumulator
__device__ float g_h[TOKV * DIMV];                   // running hidden state
__device__ float g_xr[(size_t)TOKV * 2 * DIV];       // in_proj output (x1|res)
__device__ float g_x1[(size_t)TOKV * DIV];           // post conv+silu
__device__ float g_yg[(size_t)TOKV * DIV];           // gated y before out_proj
__device__ float g_Ad[TOKV * DSV];
__device__ float g_Bd[TOKV * DSV];
__device__ float g_ys[TOKV * DSV];
__device__ float g_basis[(size_t)TOKV * KANK];       // KAN spline basis
__device__ float g_wkan[(size_t)DIMV * KANK];        // repacked coeff (768 x 3840)

// ---------------- PTX helpers ----------------------------------------------
__device__ __forceinline__ uint32_t smem_u32(const void* p) {
    uint32_t a;
    asm("{ .reg .u64 t; cvta.to.shared.u64 t, %1; cvt.u32.u64 %0, t; }"
        : "=r"(a) : "l"(p));
    return a;
}
__device__ __forceinline__ void ldsm4(uint32_t& r0, uint32_t& r1,
                                      uint32_t& r2, uint32_t& r3, uint32_t addr)
{
    asm volatile("ldmatrix.sync.aligned.m8n8.x4.shared.b16 {%0,%1,%2,%3}, [%4];"
                 : "=r"(r0), "=r"(r1), "=r"(r2), "=r"(r3) : "r"(addr));
}
__device__ __forceinline__ uint32_t f2tf(uint32_t bits)
{
    uint32_t r;
    asm("cvt.rna.tf32.f32 %0, %1;" : "=r"(r) : "f"(__uint_as_float(bits)));
    return r;
}
__device__ __forceinline__ void mma_tf32(float* c, const uint32_t* a, const uint32_t* b)
{
    asm volatile(
        "mma.sync.aligned.m16n8k8.row.col.f32.tf32.tf32.f32 "
        "{%0,%1,%2,%3}, {%4,%5,%6,%7}, {%8,%9}, {%0,%1,%2,%3};"
        : "+f"(c[0]), "+f"(c[1]), "+f"(c[2]), "+f"(c[3])
        : "r"(a[0]), "r"(a[1]), "r"(a[2]), "r"(a[3]), "r"(b[0]), "r"(b[1]));
}
__device__ __forceinline__ void cp16(uint32_t dst, const void* src)
{
    asm volatile("cp.async.cg.shared.global [%0], [%1], 16;"
                 :: "r"(dst), "l"(src) : "memory");
}
__device__ __forceinline__ void cp_commit()
{
    asm volatile("cp.async.commit_group;" ::: "memory");
}
template<int NN> __device__ __forceinline__ void cp_wait()
{
    asm volatile("cp.async.wait_group %0;" :: "n"(NN) : "memory");
}

// ---------------- tensor-core GEMM (TF32 mma.sync) --------------------------
// C[M,N] = A[M,K] @ W[N,K]^T, fp32 in/out, tf32 MMA. M%128==0, N%128==0, K%32==0.
// 256 threads, 8 warps (2x4), warp tile 64x32, BK=32 fp32, double-buffered.
// Row pitch 144 B -> 8-row ldmatrix hits distinct bank groups (stride 36 banks).
#define APITCH 144
#define TILE_B (128 * APITCH)        // 18432
#define STAGE_B (2 * TILE_B)         // A | W = 36864
#define SMEMT (2 * STAGE_B)          // 73728

template<bool BIAS, bool ACC>
__global__ __launch_bounds__(256, 2)
void tgemm(const float* __restrict__ A, const float* __restrict__ W,
           const float* __restrict__ bias, float* __restrict__ C,
           int M, int N, int K)
{
    extern __shared__ char smem[];
    const uint32_t sb0 = smem_u32(smem);
    const int tid = threadIdx.x, lane = tid & 31, wid = tid >> 5;
    const int row0 = blockIdx.y * 128, col0 = blockIdx.x * 128;
    const int rm = (wid >> 2) * 64, cn = (wid & 3) * 32;

    const float* gA = A + (size_t)row0 * K;
    const float* gW = W + (size_t)col0 * K;

    const int lrow = tid >> 3;          // 0..31 -> 4 iters of 32 rows? (1024 loads/tile)
    const int lch  = tid & 7;           // 16B chunk 0..7

    auto issue = [&](int p, int s) {
        const int k0 = p * 32;
        const uint32_t dstb = sb0 + s * STAGE_B;
#pragma unroll
        for (int i = 0; i < 4; i++) {
            int row = lrow + i * 32;
            cp16(dstb + row * APITCH + lch * 16,
                 gA + (size_t)row * K + k0 + lch * 4);
        }
#pragma unroll
        for (int i = 0; i < 4; i++) {
            int row = lrow + i * 32;
            cp16(dstb + TILE_B + row * APITCH + lch * 16,
                 gW + (size_t)row * K + k0 + lch * 4);
        }
        cp_commit();
    };

    float acc[4][4][4];
#pragma unroll
    for (int a = 0; a < 4; a++)
#pragma unroll
        for (int b = 0; b < 4; b++)
#pragma unroll
            for (int q = 0; q < 4; q++) acc[a][b][q] = 0.f;

    // ldmatrix per-lane offsets (bytes within tile)
    // A (16x8 f32 per mt): blocks {r0-7,k0-3},{r8-15,k0-3},{r0-7,k4-7},{r8-15,k4-7}
    const uint32_t aOff = (uint32_t)(rm + ((lane >> 3) & 1) * 8 + (lane & 7)) * APITCH
                        + (lane >> 4) * 16;
    // W (16 n-rows x 8 k per bt): blocks {n0-7,k0-3},{n0-7,k4-7},{n8-15,k0-3},{n8-15,k4-7}
    const uint32_t wOff = (uint32_t)(cn + ((lane >> 4) & 1) * 8 + (lane & 7)) * APITCH
                        + ((lane >> 3) & 1) * 16;

    const int npan = K >> 5;
    issue(0, 0);

    for (int p = 0; p < npan; p++) {
        const bool more = (p + 1 < npan);
        if (more) issue(p + 1, (p + 1) & 1);
        if (more) cp_wait<1>(); else cp_wait<0>();
        __syncthreads();

        const uint32_t sbase = sb0 + (p & 1) * STAGE_B;
#pragma unroll
        for (int ks = 0; ks < 4; ks++) {
            const uint32_t kb = ks * 32;          // 8 f32 = 32 B
            uint32_t Af[4][4], Wf[4][2];
#pragma unroll
            for (int mt = 0; mt < 4; mt++) {
                ldsm4(Af[mt][0], Af[mt][1], Af[mt][2], Af[mt][3],
                      sbase + aOff + mt * (16 * APITCH) + kb);
#pragma unroll
                for (int q = 0; q < 4; q++) Af[mt][q] = f2tf(Af[mt][q]);
            }
#pragma unroll
            for (int bt = 0; bt < 2; bt++) {
                uint32_t r0, r1, r2, r3;
                ldsm4(r0, r1, r2, r3,
                      sbase + TILE_B + wOff + bt * (16 * APITCH) + kb);
                Wf[bt * 2][0] = f2tf(r0); Wf[bt * 2][1] = f2tf(r1);
                Wf[bt * 2 + 1][0] = f2tf(r2); Wf[bt * 2 + 1][1] = f2tf(r3);
            }
#pragma unroll
            for (int mt = 0; mt < 4; mt++)
#pragma unroll
                for (int nt = 0; nt < 4; nt++)
                    mma_tf32(acc[mt][nt], Af[mt], Wf[nt]);
        }
        __syncthreads();
    }

    // epilogue
#pragma unroll
    for (int mt = 0; mt < 4; mt++) {
#pragma unroll
        for (int nt = 0; nt < 4; nt++) {
            int r = row0 + rm + mt * 16 + (lane >> 2);
            int c = col0 + cn + nt * 8 + (lane & 3) * 2;
            float bx = 0.f, by = 0.f;
            if (BIAS) { bx = bias[c]; by = bias[c + 1]; }
#pragma unroll
            for (int half = 0; half < 2; half++) {
                float* dst = C + (size_t)(r + half * 8) * N + c;
                float vx = acc[mt][nt][half * 2 + 0] + bx;
                float vy = acc[mt][nt][half * 2 + 1] + by;
                if (ACC) { vx += dst[0]; vy += dst[1]; }
                *reinterpret_cast<float2*>(dst) = make_float2(vx, vy);
            }
        }
    }
}

// ---------------- elementwise / small kernels ------------------------------

__global__ void im2col_k(const float* __restrict__ x)
{
    int idx = blockIdx.x * blockDim.x + threadIdx.x;
    if (idx >= TOKV * DIMV) return;
    int col = idx % DIMV;
    int row = idx / DIMV;
    int b = row >> 8, t = row & 255;
    int py = t >> 4, px = t & 15;
    int c = col >> 8, rj = col & 255;
    int r = rj >> 4, s = rj & 15;
    g_tmp[idx] = x[(((size_t)(b * 3 + c) * 256) + py * 16 + r) * 256 + px * 16 + s];
}

__global__ void addpos_k(const float* __restrict__ pos)
{
    int idx = blockIdx.x * blockDim.x + threadIdx.x;
    if (idx >= TOKV * DIMV) return;
    int d = idx % DIMV;
    int row = idx / DIMV;
    g_h[idx] += pos[(row & 255) * DIMV + d];
}

// depthwise causal conv (kernel 4) + silu
__global__ void conv_silu_k(const float* __restrict__ cw, const float* __restrict__ cb)
{
    int idx = blockIdx.x * blockDim.x + threadIdx.x;
    if (idx >= TOKV * DIV) return;
    int c = idx % DIV;
    int row = idx / DIV;
    int l = row & 255;
    float a = cb[c];
    const float* cwc = cw + c * 4;
#pragma unroll
    for (int k = 0; k < 4; k++) {
        int l2 = l - 3 + k;
        if (l2 >= 0)
            a = fmaf(g_xr[(size_t)(row - 3 + k) * (2 * DIV) + c], cwc[k], a);
    }
    g_x1[idx] = a / (1.f + expf(-a));
}

// fused dt + Bp projection + softplus/Ad/Bd
__global__ __launch_bounds__(256)
void dtbp_k(const float* __restrict__ dtw, const float* __restrict__ dtb,
            const float* __restrict__ xpw, const float* __restrict__ alog)
{
    __shared__ float Xs[64][36];
    __shared__ float Ws2[32][33];

    const int tid = threadIdx.x;
    const int lane = tid & 31;
    const int wid = tid >> 5;
    const int row0 = blockIdx.x * 64;

    const int xrow = tid >> 3;
    const int xk4  = (tid & 7) * 4;

    float acc[8];
#pragma unroll
    for (int r = 0; r < 8; r++) acc[r] = 0.f;

    const float* wsrc = (xrow < 16)
        ? (dtw + (size_t)xrow * DIV)
        : (xpw + (size_t)xrow * DIV);

    for (int kt = 0; kt < DIV; kt += 32) {
        float4 xa = *(const float4*)(g_x1 + (size_t)(row0 + xrow) * DIV + kt + xk4);
        float4 xb = *(const float4*)(g_x1 + (size_t)(row0 + 32 + xrow) * DIV + kt + xk4);
        *(float4*)&Xs[xrow][xk4] = xa;
        *(float4*)&Xs[32 + xrow][xk4] = xb;
        float4 wv = *(const float4*)(wsrc + kt + xk4);
        Ws2[xrow][xk4 + 0] = wv.x; Ws2[xrow][xk4 + 1] = wv.y;
        Ws2[xrow][xk4 + 2] = wv.z; Ws2[xrow][xk4 + 3] = wv.w;
        __syncthreads();
#pragma unroll
        for (int kk = 0; kk < 32; kk++) {
            float w = Ws2[lane][kk];
#pragma unroll
            for (int r = 0; r < 8; r++)
                acc[r] = fmaf(Xs[wid * 8 + r][kk], w, acc[r]);
        }
        __syncthreads();
    }

    float dtb_v = (lane < DSV) ? dtb[lane] : 0.f;
    float negA  = (lane < DSV) ? -expf(alog[lane]) : 0.f;

#pragma unroll
    for (int r = 0; r < 8; r++) {
        int row = row0 + wid * 8 + r;
        const float* xr = g_x1 + (size_t)row * DIV;
        float s = xr[lane] + xr[lane + 32] + xr[lane + 64];
#pragma unroll
        for (int o = 16; o; o >>= 1) s += __shfl_xor_sync(0xffffffffu, s, o);
        float u = s * (1.f / 96.f);
        float bp = __shfl_sync(0xffffffffu, acc[r], (lane & 15) + 16);
        if (lane < DSV) {
            float raw = acc[r] + dtb_v;
            float dtv = fmaxf(raw, 0.f) + log1pf(expf(-fabsf(raw)));
            g_Ad[row * DSV + lane] = expf(negA * dtv);
            g_Bd[row * DSV + lane] = dtv * bp * u;
        }
    }
}

__global__ void scan_k()
{
    int tid = blockIdx.x * blockDim.x + threadIdx.x;
    if (tid >= 32 * DSV) return;
    int b = tid >> 4, n = tid & 15;
    float s = 0.f;
    size_t base = (size_t)b * LV * DSV + n;
    for (int l = 0; l < LV; l++) {
        size_t idx = base + (size_t)l * DSV;
        s = fmaf(s, g_Ad[idx], g_Bd[idx]);
        g_ys[idx] = s;
    }
}

__global__ void yg_k(const float* __restrict__ Dp)
{
    int idx = blockIdx.x * blockDim.x + threadIdx.x;
    if (idx >= TOKV * DIV) return;
    int c = idx % DIV;
    int row = idx / DIV;
    float y = g_ys[row * DSV + c / 96] + g_x1[idx] * Dp[c];
    float r = g_xr[(size_t)row * (2 * DIV) + DIV + c];
    g_yg[idx] = y * (r / (1.f + expf(-r)));
}

// repack kan_coeff[j] (768,768,8) -> (768, 768*5) dense K-major
__global__ void repack_k(const float* __restrict__ coeff)
{
    int idx = blockIdx.x * blockDim.x + threadIdx.x;
    const int TOTAL = DIMV * KANK;
    if (idx >= TOTAL) return;
    int o = idx / KANK;
    int r2 = idx % KANK;
    int ii = r2 / GSV;
    int k = r2 % GSV;
    g_wkan[idx] = coeff[((size_t)o * DIMV + ii) * 8 + k];
}

__global__ void basis_k()
{
    int idx = blockIdx.x * blockDim.x + threadIdx.x;
    if (idx >= TOKV * DIMV) return;
    float xv = g_h[idx];
    size_t base = (size_t)idx * GSV;
    const float inv = 1.f / (0.4f + 1e-8f);
#pragma unroll
    for (int k = 0; k < GSV; k++) {
        float gk = -1.f + 0.4f * (float)k;
        float xs = (xv - gk) * inv;
        g_basis[base + k] = (xs >= 0.f && xs < 1.f) ? xs : 0.f;
    }
}

__global__ void resadd_k()
{
    int idx = blockIdx.x * blockDim.x + threadIdx.x;
    if (idx >= TOKV * DIMV) return;
    g_h[idx] = g_tmp[idx] + g_h[idx];
}

__global__ void ln_k(const float* __restrict__ nw, const float* __restrict__ nb,
                     float* __restrict__ out)
{
    __shared__ float sh[DIMV];
    __shared__ float sbuf[8];
    int row = blockIdx.x;
    int tid = threadIdx.x;
    int lane = tid & 31, w = tid >> 5;

    float s = 0.f;
    for (int d = tid; d < DIMV; d += 256) {
        float v = g_h[(size_t)row * DIMV + d];
        sh[d] = v; s += v;
    }
#pragma unroll
    for (int o = 16; o; o >>= 1) s += __shfl_xor_sync(0xffffffffu, s, o);
    if (lane == 0) sbuf[w] = s;
    __syncthreads();
    if (w == 0) {
        float t = (lane < 8) ? sbuf[lane] : 0.f;
#pragma unroll
        for (int o = 4; o; o >>= 1) t += __shfl_xor_sync(0xffffffffu, t, o);
        if (lane == 0) sbuf[0] = t;
    }
    __syncthreads();
    float mu = sbuf[0] * (1.f / DIMV);
    __syncthreads();

    float s2 = 0.f;
    for (int d = tid; d < DIMV; d += 256) {
        float dv = sh[d] - mu;
        s2 += dv * dv;
    }
#pragma unroll
    for (int o = 16; o; o >>= 1) s2 += __shfl_xor_sync(0xffffffffu, s2, o);
    if (lane == 0) sbuf[w] = s2;
    __syncthreads();
    if (w == 0) {
        float t = (lane < 8) ? sbuf[lane] : 0.f;
#pragma unroll
        for (int o = 4; o; o >>= 1) t += __shfl_xor_sync(0xffffffffu, t, o);
        if (lane == 0) sbuf[0] = t;
    }
    __syncthreads();
    float var = sbuf[0] * (1.f / DIMV);
    float inv = rsqrtf(var + 1e-5f);
    for (int d = tid; d < DIMV; d += 256) {
        out[(size_t)row * DIMV + d] = (sh[d] - mu) * inv * nw[d] + nb[d];
    }
}

// ---------------- host orchestration ---------------------------------------

extern "C" void kernel_launch(void* const* d_in, const int* in_sizes, int n_in,
                              void* d_out, int out_size)
{
    const float* x       = (const float*)d_in[0];
    const float* patch_w = (const float*)d_in[1];
    const float* patch_b = (const float*)d_in[2];
    const float* pos     = (const float*)d_in[3];
    const float* in_w    = (const float*)d_in[4];
    const float* conv_w  = (const float*)d_in[5];
    const float* conv_b  = (const float*)d_in[6];
    const float* xpw     = (const float*)d_in[7];
    const float* dtw     = (const float*)d_in[8];
    const float* dtb     = (const float*)d_in[9];
    const float* alog    = (const float*)d_in[10];
    const float* Dp      = (const float*)d_in[11];
    const float* ow      = (const float*)d_in[12];
    const float* kbw     = (const float*)d_in[13];
    const float* kco     = (const float*)d_in[14];
    const float* kbi     = (const float*)d_in[15];
    const float* nw      = (const float*)d_in[16];
    const float* nb      = (const float*)d_in[17];
    float* out = (float*)d_out;

    cudaFuncSetAttribute(tgemm<false, false>, cudaFuncAttributeMaxDynamicSharedMemorySize, SMEMT);
    cudaFuncSetAttribute(tgemm<true,  false>, cudaFuncAttributeMaxDynamicSharedMemorySize, SMEMT);
    cudaFuncSetAttribute(tgemm<false, true >, cudaFuncAttributeMaxDynamicSharedMemorySize, SMEMT);

    float *p_tmp, *p_h, *p_xr, *p_x1, *p_yg, *p_basis, *p_wkan;
    cudaGetSymbolAddress((void**)&p_tmp,   g_tmp);
    cudaGetSymbolAddress((void**)&p_h,     g_h);
    cudaGetSymbolAddress((void**)&p_xr,    g_xr);
    cudaGetSymbolAddress((void**)&p_x1,    g_x1);
    cudaGetSymbolAddress((void**)&p_yg,    g_yg);
    cudaGetSymbolAddress((void**)&p_basis, g_basis);
    cudaGetSymbolAddress((void**)&p_wkan,  g_wkan);

    const int T = 256;
    const int MB = TOKV / 128;   // 64

    // ---- patch embed ----
    im2col_k<<<(TOKV * DIMV + T - 1) / T, T>>>(x);
    tgemm<true, false><<<dim3(DIMV / 128, MB), T, SMEMT>>>(
        p_tmp, patch_w, patch_b, p_h, TOKV, DIMV, DIMV);
    addpos_k<<<(TOKV * DIMV + T - 1) / T, T>>>(pos);

    for (int i = 0; i < NLV; i++) {
        // in_proj: (8192,768) @ (3072,768)^T -> g_xr
        tgemm<false, false><<<dim3(2 * DIV / 128, MB), T, SMEMT>>>(
            p_h, in_w + (size_t)i * 2 * DIV * DIMV, nullptr, p_xr,
            TOKV, 2 * DIV, DIMV);
        conv_silu_k<<<(TOKV * DIV + T - 1) / T, T>>>(
            conv_w + (size_t)i * DIV * 4, conv_b + (size_t)i * DIV);
        dtbp_k<<<TOKV / 64, T>>>(
            dtw + (size_t)i * DSV * DIV, dtb + (size_t)i * DSV,
            xpw + (size_t)i * 2 * DSV * DIV, alog + (size_t)i * DSV);
        scan_k<<<2, 256>>>();
        yg_k<<<(TOKV * DIV + T - 1) / T, T>>>(Dp + (size_t)i * DIV);
        // out_proj: (8192,1536) @ (768,1536)^T -> g_h
        tgemm<false, false><<<dim3(DIMV / 128, MB), T, SMEMT>>>(
            p_yg, ow + (size_t)i * DIMV * DIV, nullptr, p_h,
            TOKV, DIMV, DIV);

        if (i % 3 == 2) {
            int j = i / 3;
            repack_k<<<(DIMV * KANK + T - 1) / T, T>>>(
                kco + (size_t)j * DIMV * DIMV * 8);
            basis_k<<<(TOKV * DIMV + T - 1) / T, T>>>();
            tgemm<true, false><<<dim3(DIMV / 128, MB), T, SMEMT>>>(
                p_h, kbw + (size_t)j * DIMV * DIMV, kbi + (size_t)j * DIMV, p_tmp,
                TOKV, DIMV, DIMV);
            tgemm<false, true><<<dim3(DIMV / 128, MB), T, SMEMT>>>(
                p_basis, p_wkan, nullptr, p_tmp,
                TOKV, DIMV, KANK);
            resadd_k<<<(TOKV * DIMV + T - 1) / T, T>>>();
        }
    }

    ln_k<<<TOKV, 256>>>(nw, nb, out);
}

// round 7
// speedup vs baseline: 6.2028x; 1.1712x over previous
#include <cuda_runtime.h>
#include <cuda_bf16.h>
#include <math.h>
#include <stdint.h>

#define DIMV 768
#define NLV 12
#define DSV 16
#define DIV 1536
#define TOKV 8192      // 32 batches * 256 tokens
#define LV 256
#define GSV 5
#define KANK (DIMV * GSV)   // 3840

// ---------------- scratch (static device globals; no allocation allowed) ----
__device__ float g_tmp[TOKV * DIMV];                 // im2col / KAN accumulator
__device__ float g_h[TOKV * DIMV];                   // running hidden state (exact)
__device__ float g_hr[TOKV * DIMV];                  // tf32-rounded copy of h
__device__ float g_xr[(size_t)TOKV * 2 * DIV];       // in_proj output (x1|res)
__device__ float g_x1[(size_t)TOKV * DIV];           // post conv+silu
__device__ float g_yg[(size_t)TOKV * DIV];           // gated y (tf32-rounded)
__device__ float g_Ad[TOKV * DSV];
__device__ float g_Bd[TOKV * DSV];
__device__ float g_ys[TOKV * DSV];
__device__ float g_basis[(size_t)TOKV * KANK];       // KAN spline basis (rounded)
__device__ float g_wkan[(size_t)DIMV * KANK];        // repacked+rounded coeff
// tf32-rounded weight staging
__device__ float g_wi[(size_t)NLV * 2 * DIV * DIMV];
__device__ float g_wo[(size_t)NLV * DIMV * DIV];
__device__ float g_wp[DIMV * DIMV];
__device__ float g_wkb[4 * DIMV * DIMV];

// ---------------- PTX helpers ----------------------------------------------
__device__ __forceinline__ uint32_t smem_u32(const void* p) {
    uint32_t a;
    asm("{ .reg .u64 t; cvta.to.shared.u64 t, %1; cvt.u32.u64 %0, t; }"
        : "=r"(a) : "l"(p));
    return a;
}
__device__ __forceinline__ void ldsm4(uint32_t& r0, uint32_t& r1,
                                      uint32_t& r2, uint32_t& r3, uint32_t addr)
{
    asm volatile("ldmatrix.sync.aligned.m8n8.x4.shared.b16 {%0,%1,%2,%3}, [%4];"
                 : "=r"(r0), "=r"(r1), "=r"(r2), "=r"(r3) : "r"(addr));
}
__device__ __forceinline__ float tf32r(float v)
{
    uint32_t r;
    asm("cvt.rna.tf32.f32 %0, %1;" : "=r"(r) : "f"(v));
    return __uint_as_float(r);
}
__device__ __forceinline__ void mma_tf32(float* c, const uint32_t* a, const uint32_t* b)
{
    asm volatile(
        "mma.sync.aligned.m16n8k8.row.col.f32.tf32.tf32.f32 "
        "{%0,%1,%2,%3}, {%4,%5,%6,%7}, {%8,%9}, {%0,%1,%2,%3};"
        : "+f"(c[0]), "+f"(c[1]), "+f"(c[2]), "+f"(c[3])
        : "r"(a[0]), "r"(a[1]), "r"(a[2]), "r"(a[3]), "r"(b[0]), "r"(b[1]));
}
__device__ __forceinline__ void cp16(uint32_t dst, const void* src)
{
    asm volatile("cp.async.cg.shared.global [%0], [%1], 16;"
                 :: "r"(dst), "l"(src) : "memory");
}
__device__ __forceinline__ void cp_commit()
{
    asm volatile("cp.async.commit_group;" ::: "memory");
}
template<int NN> __device__ __forceinline__ void cp_wait()
{
    asm volatile("cp.async.wait_group %0;" :: "n"(NN) : "memory");
}

// ---------------- tensor-core GEMM (TF32 mma.sync) --------------------------
// C[M,N] = A[M,K] @ W[N,K]^T. All operands PRE-ROUNDED to tf32 values in fp32.
// M%128==0, N%128==0, K%32==0. 256 threads, 8 warps (2x4), warp tile 64x32,
// BK=32, double-buffered cp.async. RST: additionally store tf32-rounded copy.
#define APITCH 144
#define TILE_B (128 * APITCH)        // 18432
#define STAGE_B (2 * TILE_B)         // 36864
#define SMEMT (2 * STAGE_B)          // 73728

template<bool BIAS, bool ACC, bool RST>
__global__ __launch_bounds__(256, 2)
void tgemm(const float* __restrict__ A, const float* __restrict__ W,
           const float* __restrict__ bias, float* __restrict__ C,
           float* __restrict__ Cr, int M, int N, int K)
{
    extern __shared__ char smem[];
    const uint32_t sb0 = smem_u32(smem);
    const int tid = threadIdx.x, lane = tid & 31, wid = tid >> 5;
    const int row0 = blockIdx.y * 128, col0 = blockIdx.x * 128;
    const int rm = (wid >> 2) * 64, cn = (wid & 3) * 32;

    const float* gA = A + (size_t)row0 * K;
    const float* gW = W + (size_t)col0 * K;

    const int lrow = tid >> 3;          // 0..31
    const int lch  = tid & 7;           // 16B chunk 0..7

    auto issue = [&](int p, int s) {
        const int k0 = p * 32;
        const uint32_t dstb = sb0 + s * STAGE_B;
#pragma unroll
        for (int i = 0; i < 4; i++) {
            int row = lrow + i * 32;
            cp16(dstb + row * APITCH + lch * 16,
                 gA + (size_t)row * K + k0 + lch * 4);
        }
#pragma unroll
        for (int i = 0; i < 4; i++) {
            int row = lrow + i * 32;
            cp16(dstb + TILE_B + row * APITCH + lch * 16,
                 gW + (size_t)row * K + k0 + lch * 4);
        }
        cp_commit();
    };

    float acc[4][4][4];
#pragma unroll
    for (int a = 0; a < 4; a++)
#pragma unroll
        for (int b = 0; b < 4; b++)
#pragma unroll
            for (int q = 0; q < 4; q++) acc[a][b][q] = 0.f;

    const uint32_t aOff = (uint32_t)(rm + ((lane >> 3) & 1) * 8 + (lane & 7)) * APITCH
                        + (lane >> 4) * 16;
    const uint32_t wOff = (uint32_t)(cn + ((lane >> 4) & 1) * 8 + (lane & 7)) * APITCH
                        + ((lane >> 3) & 1) * 16;

    const int npan = K >> 5;
    issue(0, 0);

    for (int p = 0; p < npan; p++) {
        const bool more = (p + 1 < npan);
        if (more) issue(p + 1, (p + 1) & 1);
        if (more) cp_wait<1>(); else cp_wait<0>();
        __syncthreads();

        const uint32_t sbase = sb0 + (p & 1) * STAGE_B;
#pragma unroll
        for (int ks = 0; ks < 4; ks++) {
            const uint32_t kb = ks * 32;
            uint32_t Af[4][4], Wf[4][2];
#pragma unroll
            for (int mt = 0; mt < 4; mt++)
                ldsm4(Af[mt][0], Af[mt][1], Af[mt][2], Af[mt][3],
                      sbase + aOff + mt * (16 * APITCH) + kb);
#pragma unroll
            for (int bt = 0; bt < 2; bt++) {
                uint32_t r0, r1, r2, r3;
                ldsm4(r0, r1, r2, r3,
                      sbase + TILE_B + wOff + bt * (16 * APITCH) + kb);
                Wf[bt * 2][0] = r0; Wf[bt * 2][1] = r1;
                Wf[bt * 2 + 1][0] = r2; Wf[bt * 2 + 1][1] = r3;
            }
#pragma unroll
            for (int mt = 0; mt < 4; mt++)
#pragma unroll
                for (int nt = 0; nt < 4; nt++)
                    mma_tf32(acc[mt][nt], Af[mt], Wf[nt]);
        }
        __syncthreads();
    }

    // epilogue
#pragma unroll
    for (int mt = 0; mt < 4; mt++) {
#pragma unroll
        for (int nt = 0; nt < 4; nt++) {
            int r = row0 + rm + mt * 16 + (lane >> 2);
            int c = col0 + cn + nt * 8 + (lane & 3) * 2;
            float bx = 0.f, by = 0.f;
            if (BIAS) { bx = bias[c]; by = bias[c + 1]; }
#pragma unroll
            for (int half = 0; half < 2; half++) {
                size_t off = (size_t)(r + half * 8) * N + c;
                float vx = acc[mt][nt][half * 2 + 0] + bx;
                float vy = acc[mt][nt][half * 2 + 1] + by;
                if (ACC) { vx += C[off]; vy += C[off + 1]; }
                *reinterpret_cast<float2*>(C + off) = make_float2(vx, vy);
                if (RST)
                    *reinterpret_cast<float2*>(Cr + off) =
                        make_float2(tf32r(vx), tf32r(vy));
            }
        }
    }
}

// ---------------- elementwise / small kernels ------------------------------

// vectorized tf32 rounding (weights): n % 4 == 0
__global__ void round4_k(const float* __restrict__ src, float* __restrict__ dst, int n4)
{
    int idx = blockIdx.x * blockDim.x + threadIdx.x;
    if (idx >= n4) return;
    float4 v = reinterpret_cast<const float4*>(src)[idx];
    v.x = tf32r(v.x); v.y = tf32r(v.y); v.z = tf32r(v.z); v.w = tf32r(v.w);
    reinterpret_cast<float4*>(dst)[idx] = v;
}

__global__ void im2col_k(const float* __restrict__ x)
{
    int idx = blockIdx.x * blockDim.x + threadIdx.x;
    if (idx >= TOKV * DIMV) return;
    int col = idx % DIMV;
    int row = idx / DIMV;
    int b = row >> 8, t = row & 255;
    int py = t >> 4, px = t & 15;
    int c = col >> 8, rj = col & 255;
    int r = rj >> 4, s = rj & 15;
    g_tmp[idx] = tf32r(x[(((size_t)(b * 3 + c) * 256) + py * 16 + r) * 256 + px * 16 + s]);
}

__global__ void addpos_k(const float* __restrict__ pos)
{
    int idx = blockIdx.x * blockDim.x + threadIdx.x;
    if (idx >= TOKV * DIMV) return;
    int d = idx % DIMV;
    int row = idx / DIMV;
    float v = g_h[idx] + pos[(row & 255) * DIMV + d];
    g_h[idx] = v;
    g_hr[idx] = tf32r(v);
}

// depthwise causal conv (kernel 4) + silu
__global__ void conv_silu_k(const float* __restrict__ cw, const float* __restrict__ cb)
{
    int idx = blockIdx.x * blockDim.x + threadIdx.x;
    if (idx >= TOKV * DIV) return;
    int c = idx % DIV;
    int row = idx / DIV;
    int l = row & 255;
    float a = cb[c];
    const float* cwc = cw + c * 4;
#pragma unroll
    for (int k = 0; k < 4; k++) {
        int l2 = l - 3 + k;
        if (l2 >= 0)
            a = fmaf(g_xr[(size_t)(row - 3 + k) * (2 * DIV) + c], cwc[k], a);
    }
    g_x1[idx] = a / (1.f + expf(-a));
}

// fused dt + Bp projection + softplus/Ad/Bd
__global__ __launch_bounds__(256)
void dtbp_k(const float* __restrict__ dtw, const float* __restrict__ dtb,
            const float* __restrict__ xpw, const float* __restrict__ alog)
{
    __shared__ float Xs[64][36];
    __shared__ float Ws2[32][33];

    const int tid = threadIdx.x;
    const int lane = tid & 31;
    const int wid = tid >> 5;
    const int row0 = blockIdx.x * 64;

    const int xrow = tid >> 3;
    const int xk4  = (tid & 7) * 4;

    float acc[8];
#pragma unroll
    for (int r = 0; r < 8; r++) acc[r] = 0.f;

    const float* wsrc = (xrow < 16)
        ? (dtw + (size_t)xrow * DIV)
        : (xpw + (size_t)xrow * DIV);

    for (int kt = 0; kt < DIV; kt += 32) {
        float4 xa = *(const float4*)(g_x1 + (size_t)(row0 + xrow) * DIV + kt + xk4);
        float4 xb = *(const float4*)(g_x1 + (size_t)(row0 + 32 + xrow) * DIV + kt + xk4);
        *(float4*)&Xs[xrow][xk4] = xa;
        *(float4*)&Xs[32 + xrow][xk4] = xb;
        float4 wv = *(const float4*)(wsrc + kt + xk4);
        Ws2[xrow][xk4 + 0] = wv.x; Ws2[xrow][xk4 + 1] = wv.y;
        Ws2[xrow][xk4 + 2] = wv.z; Ws2[xrow][xk4 + 3] = wv.w;
        __syncthreads();
#pragma unroll
        for (int kk = 0; kk < 32; kk++) {
            float w = Ws2[lane][kk];
#pragma unroll
            for (int r = 0; r < 8; r++)
                acc[r] = fmaf(Xs[wid * 8 + r][kk], w, acc[r]);
        }
        __syncthreads();
    }

    float dtb_v = (lane < DSV) ? dtb[lane] : 0.f;
    float negA  = (lane < DSV) ? -expf(alog[lane]) : 0.f;

#pragma unroll
    for (int r = 0; r < 8; r++) {
        int row = row0 + wid * 8 + r;
        const float* xr = g_x1 + (size_t)row * DIV;
        float s = xr[lane] + xr[lane + 32] + xr[lane + 64];
#pragma unroll
        for (int o = 16; o; o >>= 1) s += __shfl_xor_sync(0xffffffffu, s, o);
        float u = s * (1.f / 96.f);
        float bp = __shfl_sync(0xffffffffu, acc[r], (lane & 15) + 16);
        if (lane < DSV) {
            float raw = acc[r] + dtb_v;
            float dtv = fmaxf(raw, 0.f) + log1pf(expf(-fabsf(raw)));
            g_Ad[row * DSV + lane] = expf(negA * dtv);
            g_Bd[row * DSV + lane] = dtv * bp * u;
        }
    }
}

// warp-parallel linear-recurrence scan: one warp per (batch, state) pair.
// Composition (A,B) then (A',B'): s -> A'(As+B)+B' = (AA')s + (A'B+B').
__global__ void scan_k()   // <<<64, 256>>> : 512 warps
{
    int g = blockIdx.x * blockDim.x + threadIdx.x;
    int w = g >> 5, lane = g & 31;
    int b = w >> 4, n = w & 15;
    size_t idx0 = (size_t)b * LV * DSV + n + (size_t)(lane * 8) * DSV;

    float a[8], bb[8];
    float A = 1.f, B = 0.f;
#pragma unroll
    for (int i = 0; i < 8; i++) {
        a[i]  = g_Ad[idx0 + (size_t)i * DSV];
        bb[i] = g_Bd[idx0 + (size_t)i * DSV];
        B = B * a[i] + bb[i];
        A = A * a[i];
    }
    // inclusive scan of (A,B) across lanes
    float Ai = A, Bi = B;
#pragma unroll
    for (int o = 1; o < 32; o <<= 1) {
        float Ap = __shfl_up_sync(0xffffffffu, Ai, o);
        float Bp = __shfl_up_sync(0xffffffffu, Bi, o);
        if (lane >= o) { Bi = Bp * Ai + Bi; Ai = Ai * Ap; }
    }
    float sin = __shfl_up_sync(0xffffffffu, Bi, 1);
    if (lane == 0) sin = 0.f;
    float s = sin;
#pragma unroll
    for (int i = 0; i < 8; i++) {
        s = s * a[i] + bb[i];
        g_ys[idx0 + (size_t)i * DSV] = s;
    }
}

__global__ void yg_k(const float* __restrict__ Dp)
{
    int idx = blockIdx.x * blockDim.x + threadIdx.x;
    if (idx >= TOKV * DIV) return;
    int c = idx % DIV;
    int row = idx / DIV;
    float y = g_ys[row * DSV + c / 96] + g_x1[idx] * Dp[c];
    float r = g_xr[(size_t)row * (2 * DIV) + DIV + c];
    g_yg[idx] = tf32r(y * (r / (1.f + expf(-r))));
}

// repack kan_coeff[j] (768,768,8) -> (768, 768*5) dense K-major, tf32-rounded
__global__ void repack_k(const float* __restrict__ coeff)
{
    int idx = blockIdx.x * blockDim.x + threadIdx.x;
    const int TOTAL = DIMV * KANK;
    if (idx >= TOTAL) return;
    int o = idx / KANK;
    int r2 = idx % KANK;
    int ii = r2 / GSV;
    int k = r2 % GSV;
    g_wkan[idx] = tf32r(coeff[((size_t)o * DIMV + ii) * 8 + k]);
}

__global__ void basis_k()
{
    int idx = blockIdx.x * blockDim.x + threadIdx.x;
    if (idx >= TOKV * DIMV) return;
    float xv = g_h[idx];
    size_t base = (size_t)idx * GSV;
    const float inv = 1.f / (0.4f + 1e-8f);
#pragma unroll
    for (int k = 0; k < GSV; k++) {
        float gk = -1.f + 0.4f * (float)k;
        float xs = (xv - gk) * inv;
        g_basis[base + k] = (xs >= 0.f && xs < 1.f) ? tf32r(xs) : 0.f;
    }
}

__global__ void resadd_k()
{
    int idx = blockIdx.x * blockDim.x + threadIdx.x;
    if (idx >= TOKV * DIMV) return;
    float v = g_tmp[idx] + g_h[idx];
    g_h[idx] = v;
    g_hr[idx] = tf32r(v);
}

__global__ void ln_k(const float* __restrict__ nw, const float* __restrict__ nb,
                     float* __restrict__ out)
{
    __shared__ float sh[DIMV];
    __shared__ float sbuf[8];
    int row = blockIdx.x;
    int tid = threadIdx.x;
    int lane = tid & 31, w = tid >> 5;

    float s = 0.f;
    for (int d = tid; d < DIMV; d += 256) {
        float v = g_h[(size_t)row * DIMV + d];
        sh[d] = v; s += v;
    }
#pragma unroll
    for (int o = 16; o; o >>= 1) s += __shfl_xor_sync(0xffffffffu, s, o);
    if (lane == 0) sbuf[w] = s;
    __syncthreads();
    if (w == 0) {
        float t = (lane < 8) ? sbuf[lane] : 0.f;
#pragma unroll
        for (int o = 4; o; o >>= 1) t += __shfl_xor_sync(0xffffffffu, t, o);
        if (lane == 0) sbuf[0] = t;
    }
    __syncthreads();
    float mu = sbuf[0] * (1.f / DIMV);
    __syncthreads();

    float s2 = 0.f;
    for (int d = tid; d < DIMV; d += 256) {
        float dv = sh[d] - mu;
        s2 += dv * dv;
    }
#pragma unroll
    for (int o = 16; o; o >>= 1) s2 += __shfl_xor_sync(0xffffffffu, s2, o);
    if (lane == 0) sbuf[w] = s2;
    __syncthreads();
    if (w == 0) {
        float t = (lane < 8) ? sbuf[lane] : 0.f;
#pragma unroll
        for (int o = 4; o; o >>= 1) t += __shfl_xor_sync(0xffffffffu, t, o);
        if (lane == 0) sbuf[0] = t;
    }
    __syncthreads();
    float var = sbuf[0] * (1.f / DIMV);
    float inv = rsqrtf(var + 1e-5f);
    for (int d = tid; d < DIMV; d += 256) {
        out[(size_t)row * DIMV + d] = (sh[d] - mu) * inv * nw[d] + nb[d];
    }
}

// ---------------- host orchestration ---------------------------------------

extern "C" void kernel_launch(void* const* d_in, const int* in_sizes, int n_in,
                              void* d_out, int out_size)
{
    const float* x       = (const float*)d_in[0];
    const float* patch_w = (const float*)d_in[1];
    const float* patch_b = (const float*)d_in[2];
    const float* pos     = (const float*)d_in[3];
    const float* in_w    = (const float*)d_in[4];
    const float* conv_w  = (const float*)d_in[5];
    const float* conv_b  = (const float*)d_in[6];
    const float* xpw     = (const float*)d_in[7];
    const float* dtw     = (const float*)d_in[8];
    const float* dtb     = (const float*)d_in[9];
    const float* alog    = (const float*)d_in[10];
    const float* Dp      = (const float*)d_in[11];
    const float* ow      = (const float*)d_in[12];
    const float* kbw     = (const float*)d_in[13];
    const float* kco     = (const float*)d_in[14];
    const float* kbi     = (const float*)d_in[15];
    const float* nw      = (const float*)d_in[16];
    const float* nb      = (const float*)d_in[17];
    float* out = (float*)d_out;

    cudaFuncSetAttribute(tgemm<false, false, false>, cudaFuncAttributeMaxDynamicSharedMemorySize, SMEMT);
    cudaFuncSetAttribute(tgemm<false, false, true >, cudaFuncAttributeMaxDynamicSharedMemorySize, SMEMT);
    cudaFuncSetAttribute(tgemm<true,  false, false>, cudaFuncAttributeMaxDynamicSharedMemorySize, SMEMT);
    cudaFuncSetAttribute(tgemm<false, true,  false>, cudaFuncAttributeMaxDynamicSharedMemorySize, SMEMT);

    float *p_tmp, *p_h, *p_hr, *p_xr, *p_x1, *p_yg, *p_basis, *p_wkan;
    float *p_wi, *p_wo, *p_wp, *p_wkb;
    cudaGetSymbolAddress((void**)&p_tmp,   g_tmp);
    cudaGetSymbolAddress((void**)&p_h,     g_h);
    cudaGetSymbolAddress((void**)&p_hr,    g_hr);
    cudaGetSymbolAddress((void**)&p_xr,    g_xr);
    cudaGetSymbolAddress((void**)&p_x1,    g_x1);
    cudaGetSymbolAddress((void**)&p_yg,    g_yg);
    cudaGetSymbolAddress((void**)&p_basis, g_basis);
    cudaGetSymbolAddress((void**)&p_wkan,  g_wkan);
    cudaGetSymbolAddress((void**)&p_wi,    g_wi);
    cudaGetSymbolAddress((void**)&p_wo,    g_wo);
    cudaGetSymbolAddress((void**)&p_wp,    g_wp);
    cudaGetSymbolAddress((void**)&p_wkb,   g_wkb);

    const int T = 256;
    const int MB = TOKV / 128;   // 64

    // ---- weight tf32 rounding (per call; weights are inputs) ----
    {
        int n4;
        n4 = NLV * 2 * DIV * DIMV / 4;
        round4_k<<<(n4 + T - 1) / T, T>>>(in_w, p_wi, n4);
        n4 = NLV * DIMV * DIV / 4;
        round4_k<<<(n4 + T - 1) / T, T>>>(ow, p_wo, n4);
        n4 = DIMV * DIMV / 4;
        round4_k<<<(n4 + T - 1) / T, T>>>(patch_w, p_wp, n4);
        n4 = 4 * DIMV * DIMV / 4;
        round4_k<<<(n4 + T - 1) / T, T>>>(kbw, p_wkb, n4);
    }

    // ---- patch embed ----
    im2col_k<<<(TOKV * DIMV + T - 1) / T, T>>>(x);
    tgemm<true, false, false><<<dim3(DIMV / 128, MB), T, SMEMT>>>(
        p_tmp, p_wp, patch_b, p_h, nullptr, TOKV, DIMV, DIMV);
    addpos_k<<<(TOKV * DIMV + T - 1) / T, T>>>(pos);

    for (int i = 0; i < NLV; i++) {
        // in_proj: (8192,768) @ (3072,768)^T -> g_xr
        tgemm<false, false, false><<<dim3(2 * DIV / 128, MB), T, SMEMT>>>(
            p_hr, p_wi + (size_t)i * 2 * DIV * DIMV, nullptr, p_xr, nullptr,
            TOKV, 2 * DIV, DIMV);
        conv_silu_k<<<(TOKV * DIV + T - 1) / T, T>>>(
            conv_w + (size_t)i * DIV * 4, conv_b + (size_t)i * DIV);
        dtbp_k<<<TOKV / 64, T>>>(
            dtw + (size_t)i * DSV * DIV, dtb + (size_t)i * DSV,
            xpw + (size_t)i * 2 * DSV * DIV, alog + (size_t)i * DSV);
        scan_k<<<64, 256>>>();
        yg_k<<<(TOKV * DIV + T - 1) / T, T>>>(Dp + (size_t)i * DIV);
        // out_proj: (8192,1536) @ (768,1536)^T -> g_h (+ rounded g_hr)
        tgemm<false, false, true><<<dim3(DIMV / 128, MB), T, SMEMT>>>(
            p_yg, p_wo + (size_t)i * DIMV * DIV, nullptr, p_h, p_hr,
            TOKV, DIMV, DIV);

        if (i % 3 == 2) {
            int j = i / 3;
            repack_k<<<(DIMV * KANK + T - 1) / T, T>>>(
                kco + (size_t)j * DIMV * DIMV * 8);
            basis_k<<<(TOKV * DIMV + T - 1) / T, T>>>();
            tgemm<true, false, false><<<dim3(DIMV / 128, MB), T, SMEMT>>>(
                p_hr, p_wkb + (size_t)j * DIMV * DIMV, kbi + (size_t)j * DIMV,
                p_tmp, nullptr, TOKV, DIMV, DIMV);
            tgemm<false, true, false><<<dim3(DIMV / 128, MB), T, SMEMT>>>(
                p_basis, p_wkan, nullptr, p_tmp, nullptr,
                TOKV, DIMV, KANK);
            resadd_k<<<(TOKV * DIMV + T - 1) / T, T>>>();
        }
    }

    ln_k<<<TOKV, 256>>>(nw, nb, out);
}

// round 8
// speedup vs baseline: 6.3897x; 1.0301x over previous
#include <cuda_runtime.h>
#include <cuda_bf16.h>
#include <math.h>
#include <stdint.h>

#define DIMV 768
#define NLV 12
#define DSV 16
#define DIV 1536
#define TOKV 8192      // 32 batches * 256 tokens
#define LV 256
#define GSV 5
#define KANK (DIMV * GSV)   // 3840

// ---------------- scratch (static device globals; no allocation allowed) ----
__device__ float g_tmp[TOKV * DIMV];                 // im2col / KAN accumulator
__device__ float g_h[TOKV * DIMV];                   // running hidden state (exact)
__device__ float g_hr[TOKV * DIMV];                  // tf32-rounded copy of h
__device__ float g_xr[(size_t)TOKV * 2 * DIV];       // in_proj output (x1|res)
__device__ float g_x1[(size_t)TOKV * DIV];           // post conv+silu
__device__ float g_yg[(size_t)TOKV * DIV];           // gated y (tf32-rounded)
__device__ float g_Ad[TOKV * DSV];
__device__ float g_Bd[TOKV * DSV];
__device__ float g_ys[TOKV * DSV];
__device__ float g_basis[(size_t)TOKV * KANK];       // KAN spline basis (rounded)
__device__ float g_wkan[(size_t)DIMV * KANK];        // repacked+rounded coeff
// tf32-rounded weight staging
__device__ float g_wi[(size_t)NLV * 2 * DIV * DIMV];
__device__ float g_wo[(size_t)NLV * DIMV * DIV];
__device__ float g_wp[DIMV * DIMV];
__device__ float g_wkb[4 * DIMV * DIMV];

// ---------------- PTX helpers ----------------------------------------------
__device__ __forceinline__ uint32_t smem_u32(const void* p) {
    uint32_t a;
    asm("{ .reg .u64 t; cvta.to.shared.u64 t, %1; cvt.u32.u64 %0, t; }"
        : "=r"(a) : "l"(p));
    return a;
}
__device__ __forceinline__ void ldsm4(uint32_t& r0, uint32_t& r1,
                                      uint32_t& r2, uint32_t& r3, uint32_t addr)
{
    asm volatile("ldmatrix.sync.aligned.m8n8.x4.shared.b16 {%0,%1,%2,%3}, [%4];"
                 : "=r"(r0), "=r"(r1), "=r"(r2), "=r"(r3) : "r"(addr));
}
__device__ __forceinline__ float tf32r(float v)
{
    uint32_t r;
    asm("cvt.rna.tf32.f32 %0, %1;" : "=r"(r) : "f"(v));
    return __uint_as_float(r);
}
__device__ __forceinline__ float4 tf32r4(float4 v)
{
    v.x = tf32r(v.x); v.y = tf32r(v.y); v.z = tf32r(v.z); v.w = tf32r(v.w);
    return v;
}
__device__ __forceinline__ void mma_tf32(float* c, const uint32_t* a, const uint32_t* b)
{
    asm volatile(
        "mma.sync.aligned.m16n8k8.row.col.f32.tf32.tf32.f32 "
        "{%0,%1,%2,%3}, {%4,%5,%6,%7}, {%8,%9}, {%0,%1,%2,%3};"
        : "+f"(c[0]), "+f"(c[1]), "+f"(c[2]), "+f"(c[3])
        : "r"(a[0]), "r"(a[1]), "r"(a[2]), "r"(a[3]), "r"(b[0]), "r"(b[1]));
}
__device__ __forceinline__ void cp16(uint32_t dst, const void* src)
{
    asm volatile("cp.async.cg.shared.global [%0], [%1], 16;"
                 :: "r"(dst), "l"(src) : "memory");
}
__device__ __forceinline__ void cp_commit()
{
    asm volatile("cp.async.commit_group;" ::: "memory");
}
template<int NN> __device__ __forceinline__ void cp_wait()
{
    asm volatile("cp.async.wait_group %0;" :: "n"(NN) : "memory");
}

// ---------------- tensor-core GEMM (TF32 mma.sync) --------------------------
#define APITCH 144
#define TILE_B (128 * APITCH)        // 18432
#define STAGE_B (2 * TILE_B)         // 36864
#define SMEMT (2 * STAGE_B)          // 73728

template<bool BIAS, bool ACC, bool RST>
__global__ __launch_bounds__(256, 2)
void tgemm(const float* __restrict__ A, const float* __restrict__ W,
           const float* __restrict__ bias, float* __restrict__ C,
           float* __restrict__ Cr, int M, int N, int K)
{
    extern __shared__ char smem[];
    const uint32_t sb0 = smem_u32(smem);
    const int tid = threadIdx.x, lane = tid & 31, wid = tid >> 5;
    const int row0 = blockIdx.y * 128, col0 = blockIdx.x * 128;
    const int rm = (wid >> 2) * 64, cn = (wid & 3) * 32;

    const float* gA = A + (size_t)row0 * K;
    const float* gW = W + (size_t)col0 * K;

    const int lrow = tid >> 3;          // 0..31
    const int lch  = tid & 7;           // 16B chunk 0..7

    auto issue = [&](int p, int s) {
        const int k0 = p * 32;
        const uint32_t dstb = sb0 + s * STAGE_B;
#pragma unroll
        for (int i = 0; i < 4; i++) {
            int row = lrow + i * 32;
            cp16(dstb + row * APITCH + lch * 16,
                 gA + (size_t)row * K + k0 + lch * 4);
        }
#pragma unroll
        for (int i = 0; i < 4; i++) {
            int row = lrow + i * 32;
            cp16(dstb + TILE_B + row * APITCH + lch * 16,
                 gW + (size_t)row * K + k0 + lch * 4);
        }
        cp_commit();
    };

    float acc[4][4][4];
#pragma unroll
    for (int a = 0; a < 4; a++)
#pragma unroll
        for (int b = 0; b < 4; b++)
#pragma unroll
            for (int q = 0; q < 4; q++) acc[a][b][q] = 0.f;

    const uint32_t aOff = (uint32_t)(rm + ((lane >> 3) & 1) * 8 + (lane & 7)) * APITCH
                        + (lane >> 4) * 16;
    const uint32_t wOff = (uint32_t)(cn + ((lane >> 4) & 1) * 8 + (lane & 7)) * APITCH
                        + ((lane >> 3) & 1) * 16;

    const int npan = K >> 5;
    issue(0, 0);

    for (int p = 0; p < npan; p++) {
        const bool more = (p + 1 < npan);
        if (more) issue(p + 1, (p + 1) & 1);
        if (more) cp_wait<1>(); else cp_wait<0>();
        __syncthreads();

        const uint32_t sbase = sb0 + (p & 1) * STAGE_B;
#pragma unroll
        for (int ks = 0; ks < 4; ks++) {
            const uint32_t kb = ks * 32;
            uint32_t Af[4][4], Wf[4][2];
#pragma unroll
            for (int mt = 0; mt < 4; mt++)
                ldsm4(Af[mt][0], Af[mt][1], Af[mt][2], Af[mt][3],
                      sbase + aOff + mt * (16 * APITCH) + kb);
#pragma unroll
            for (int bt = 0; bt < 2; bt++) {
                uint32_t r0, r1, r2, r3;
                ldsm4(r0, r1, r2, r3,
                      sbase + TILE_B + wOff + bt * (16 * APITCH) + kb);
                Wf[bt * 2][0] = r0; Wf[bt * 2][1] = r1;
                Wf[bt * 2 + 1][0] = r2; Wf[bt * 2 + 1][1] = r3;
            }
#pragma unroll
            for (int mt = 0; mt < 4; mt++)
#pragma unroll
                for (int nt = 0; nt < 4; nt++)
                    mma_tf32(acc[mt][nt], Af[mt], Wf[nt]);
        }
        __syncthreads();
    }

    // epilogue
#pragma unroll
    for (int mt = 0; mt < 4; mt++) {
#pragma unroll
        for (int nt = 0; nt < 4; nt++) {
            int r = row0 + rm + mt * 16 + (lane >> 2);
            int c = col0 + cn + nt * 8 + (lane & 3) * 2;
            float bx = 0.f, by = 0.f;
            if (BIAS) { bx = bias[c]; by = bias[c + 1]; }
#pragma unroll
            for (int half = 0; half < 2; half++) {
                size_t off = (size_t)(r + half * 8) * N + c;
                float vx = acc[mt][nt][half * 2 + 0] + bx;
                float vy = acc[mt][nt][half * 2 + 1] + by;
                if (ACC) { vx += C[off]; vy += C[off + 1]; }
                *reinterpret_cast<float2*>(C + off) = make_float2(vx, vy);
                if (RST)
                    *reinterpret_cast<float2*>(Cr + off) =
                        make_float2(tf32r(vx), tf32r(vy));
            }
        }
    }
}

// ---------------- elementwise / small kernels (float4-vectorized) ----------

__global__ void round4_k(const float* __restrict__ src, float* __restrict__ dst, int n4)
{
    int idx = blockIdx.x * blockDim.x + threadIdx.x;
    if (idx >= n4) return;
    reinterpret_cast<float4*>(dst)[idx] =
        tf32r4(reinterpret_cast<const float4*>(src)[idx]);
}

__global__ void im2col_k(const float* __restrict__ x)
{
    int idx = blockIdx.x * blockDim.x + threadIdx.x;    // over TOKV*DIMV/4
    if (idx >= TOKV * DIMV / 4) return;
    int col4 = (idx % (DIMV / 4)) * 4;
    int row  = idx / (DIMV / 4);
    int b = row >> 8, t = row & 255;
    int py = t >> 4, px = t & 15;
    int c = col4 >> 8, rj = col4 & 255;
    int r = rj >> 4, s = rj & 15;    // s, s+1, s+2, s+3 contiguous in source
    const float4 v = *reinterpret_cast<const float4*>(
        x + (((size_t)(b * 3 + c) * 256) + py * 16 + r) * 256 + px * 16 + s);
    reinterpret_cast<float4*>(g_tmp)[idx] = tf32r4(v);
}

__global__ void addpos_k(const float* __restrict__ pos)
{
    int idx = blockIdx.x * blockDim.x + threadIdx.x;    // over TOKV*DIMV/4
    if (idx >= TOKV * DIMV / 4) return;
    int d4  = idx % (DIMV / 4);
    int row = idx / (DIMV / 4);
    float4 h = reinterpret_cast<const float4*>(g_h)[idx];
    float4 p = reinterpret_cast<const float4*>(pos)[(row & 255) * (DIMV / 4) + d4];
    h.x += p.x; h.y += p.y; h.z += p.z; h.w += p.w;
    reinterpret_cast<float4*>(g_h)[idx] = h;
    reinterpret_cast<float4*>(g_hr)[idx] = tf32r4(h);
}

// depthwise causal conv (kernel 4) + silu, 4 channels / thread
__global__ void conv_silu_k(const float* __restrict__ cw, const float* __restrict__ cb)
{
    int idx = blockIdx.x * blockDim.x + threadIdx.x;    // over TOKV*DIV/4
    if (idx >= TOKV * DIV / 4) return;
    int c4  = (idx % (DIV / 4)) * 4;
    int row = idx / (DIV / 4);
    int l = row & 255;

    float4 a = *reinterpret_cast<const float4*>(cb + c4);
    // taps for each channel are contiguous: cw[c*4 + k]
    float4 w0 = *reinterpret_cast<const float4*>(cw + (c4 + 0) * 4);
    float4 w1 = *reinterpret_cast<const float4*>(cw + (c4 + 1) * 4);
    float4 w2 = *reinterpret_cast<const float4*>(cw + (c4 + 2) * 4);
    float4 w3 = *reinterpret_cast<const float4*>(cw + (c4 + 3) * 4);
    const float* wk[4] = { (const float*)&w0, (const float*)&w1,
                           (const float*)&w2, (const float*)&w3 };
#pragma unroll
    for (int k = 0; k < 4; k++) {
        int l2 = l - 3 + k;
        if (l2 >= 0) {
            float4 xv = *reinterpret_cast<const float4*>(
                g_xr + (size_t)(row - 3 + k) * (2 * DIV) + c4);
            a.x = fmaf(xv.x, wk[0][k], a.x);
            a.y = fmaf(xv.y, wk[1][k], a.y);
            a.z = fmaf(xv.z, wk[2][k], a.z);
            a.w = fmaf(xv.w, wk[3][k], a.w);
        }
    }
    a.x = a.x / (1.f + expf(-a.x));
    a.y = a.y / (1.f + expf(-a.y));
    a.z = a.z / (1.f + expf(-a.z));
    a.w = a.w / (1.f + expf(-a.w));
    reinterpret_cast<float4*>(g_x1)[idx] = a;
}

// fused dt + Bp projection + softplus/Ad/Bd
__global__ __launch_bounds__(256)
void dtbp_k(const float* __restrict__ dtw, const float* __restrict__ dtb,
            const float* __restrict__ xpw, const float* __restrict__ alog)
{
    __shared__ float Xs[64][36];
    __shared__ float Ws2[32][33];

    const int tid = threadIdx.x;
    const int lane = tid & 31;
    const int wid = tid >> 5;
    const int row0 = blockIdx.x * 64;

    const int xrow = tid >> 3;
    const int xk4  = (tid & 7) * 4;

    float acc[8];
#pragma unroll
    for (int r = 0; r < 8; r++) acc[r] = 0.f;

    const float* wsrc = (xrow < 16)
        ? (dtw + (size_t)xrow * DIV)
        : (xpw + (size_t)xrow * DIV);

    for (int kt = 0; kt < DIV; kt += 32) {
        float4 xa = *(const float4*)(g_x1 + (size_t)(row0 + xrow) * DIV + kt + xk4);
        float4 xb = *(const float4*)(g_x1 + (size_t)(row0 + 32 + xrow) * DIV + kt + xk4);
        *(float4*)&Xs[xrow][xk4] = xa;
        *(float4*)&Xs[32 + xrow][xk4] = xb;
        float4 wv = *(const float4*)(wsrc + kt + xk4);
        Ws2[xrow][xk4 + 0] = wv.x; Ws2[xrow][xk4 + 1] = wv.y;
        Ws2[xrow][xk4 + 2] = wv.z; Ws2[xrow][xk4 + 3] = wv.w;
        __syncthreads();
#pragma unroll
        for (int kk = 0; kk < 32; kk++) {
            float w = Ws2[lane][kk];
#pragma unroll
            for (int r = 0; r < 8; r++)
                acc[r] = fmaf(Xs[wid * 8 + r][kk], w, acc[r]);
        }
        __syncthreads();
    }

    float dtb_v = (lane < DSV) ? dtb[lane] : 0.f;
    float negA  = (lane < DSV) ? -expf(alog[lane]) : 0.f;

#pragma unroll
    for (int r = 0; r < 8; r++) {
        int row = row0 + wid * 8 + r;
        const float* xr = g_x1 + (size_t)row * DIV;
        float s = xr[lane] + xr[lane + 32] + xr[lane + 64];
#pragma unroll
        for (int o = 16; o; o >>= 1) s += __shfl_xor_sync(0xffffffffu, s, o);
        float u = s * (1.f / 96.f);
        float bp = __shfl_sync(0xffffffffu, acc[r], (lane & 15) + 16);
        if (lane < DSV) {
            float raw = acc[r] + dtb_v;
            float dtv = fmaxf(raw, 0.f) + log1pf(expf(-fabsf(raw)));
            g_Ad[row * DSV + lane] = expf(negA * dtv);
            g_Bd[row * DSV + lane] = dtv * bp * u;
        }
    }
}

// warp-parallel linear-recurrence scan: one warp per (batch, state) pair.
__global__ void scan_k()   // <<<64, 256>>> : 512 warps
{
    int g = blockIdx.x * blockDim.x + threadIdx.x;
    int w = g >> 5, lane = g & 31;
    int b = w >> 4, n = w & 15;
    size_t idx0 = (size_t)b * LV * DSV + n + (size_t)(lane * 8) * DSV;

    float a[8], bb[8];
    float A = 1.f, B = 0.f;
#pragma unroll
    for (int i = 0; i < 8; i++) {
        a[i]  = g_Ad[idx0 + (size_t)i * DSV];
        bb[i] = g_Bd[idx0 + (size_t)i * DSV];
        B = B * a[i] + bb[i];
        A = A * a[i];
    }
    float Ai = A, Bi = B;
#pragma unroll
    for (int o = 1; o < 32; o <<= 1) {
        float Ap = __shfl_up_sync(0xffffffffu, Ai, o);
        float Bp = __shfl_up_sync(0xffffffffu, Bi, o);
        if (lane >= o) { Bi = Bp * Ai + Bi; Ai = Ai * Ap; }
    }
    float sin = __shfl_up_sync(0xffffffffu, Bi, 1);
    if (lane == 0) sin = 0.f;
    float s = sin;
#pragma unroll
    for (int i = 0; i < 8; i++) {
        s = s * a[i] + bb[i];
        g_ys[idx0 + (size_t)i * DSV] = s;
    }
}

__global__ void yg_k(const float* __restrict__ Dp)
{
    int idx = blockIdx.x * blockDim.x + threadIdx.x;    // over TOKV*DIV/4
    if (idx >= TOKV * DIV / 4) return;
    int c4  = (idx % (DIV / 4)) * 4;
    int row = idx / (DIV / 4);
    float ys = g_ys[row * DSV + c4 / 96];               // constant across the 4
    float4 x1 = reinterpret_cast<const float4*>(g_x1)[idx];
    float4 dp = *reinterpret_cast<const float4*>(Dp + c4);
    float4 rs = *reinterpret_cast<const float4*>(
        g_xr + (size_t)row * (2 * DIV) + DIV + c4);
    float4 o;
    o.x = tf32r((ys + x1.x * dp.x) * (rs.x / (1.f + expf(-rs.x))));
    o.y = tf32r((ys + x1.y * dp.y) * (rs.y / (1.f + expf(-rs.y))));
    o.z = tf32r((ys + x1.z * dp.z) * (rs.z / (1.f + expf(-rs.z))));
    o.w = tf32r((ys + x1.w * dp.w) * (rs.w / (1.f + expf(-rs.w))));
    reinterpret_cast<float4*>(g_yg)[idx] = o;
}

// repack kan_coeff[j] (768,768,8) -> (768, 768*5) dense K-major, tf32-rounded
__global__ void repack_k(const float* __restrict__ coeff)
{
    int idx = blockIdx.x * blockDim.x + threadIdx.x;
    const int TOTAL = DIMV * KANK;
    if (idx >= TOTAL) return;
    int o = idx / KANK;
    int r2 = idx % KANK;
    int ii = r2 / GSV;
    int k = r2 % GSV;
    g_wkan[idx] = tf32r(coeff[((size_t)o * DIMV + ii) * 8 + k]);
}

// 4 h-values per thread -> 20 basis values = 5 aligned float4 stores
__global__ void basis_k()
{
    int idx = blockIdx.x * blockDim.x + threadIdx.x;    // over TOKV*DIMV/4
    if (idx >= TOKV * DIMV / 4) return;
    float4 h = reinterpret_cast<const float4*>(g_h)[idx];
    const float* hv = (const float*)&h;
    float outv[20];
    const float inv = 1.f / (0.4f + 1e-8f);
#pragma unroll
    for (int e = 0; e < 4; e++) {
        float xv = hv[e];
#pragma unroll
        for (int k = 0; k < GSV; k++) {
            float gk = -1.f + 0.4f * (float)k;
            float xs = (xv - gk) * inv;
            outv[e * GSV + k] = (xs >= 0.f && xs < 1.f) ? tf32r(xs) : 0.f;
        }
    }
    float4* dst = reinterpret_cast<float4*>(g_basis + (size_t)idx * 20);
#pragma unroll
    for (int q = 0; q < 5; q++)
        dst[q] = make_float4(outv[q * 4], outv[q * 4 + 1],
                             outv[q * 4 + 2], outv[q * 4 + 3]);
}

__global__ void resadd_k()
{
    int idx = blockIdx.x * blockDim.x + threadIdx.x;    // over TOKV*DIMV/4
    if (idx >= TOKV * DIMV / 4) return;
    float4 t = reinterpret_cast<const float4*>(g_tmp)[idx];
    float4 h = reinterpret_cast<const float4*>(g_h)[idx];
    h.x += t.x; h.y += t.y; h.z += t.z; h.w += t.w;
    reinterpret_cast<float4*>(g_h)[idx] = h;
    reinterpret_cast<float4*>(g_hr)[idx] = tf32r4(h);
}

__global__ void ln_k(const float* __restrict__ nw, const float* __restrict__ nb,
                     float* __restrict__ out)
{
    __shared__ float sh[DIMV];
    __shared__ float sbuf[8];
    int row = blockIdx.x;
    int tid = threadIdx.x;
    int lane = tid & 31, w = tid >> 5;

    float s = 0.f;
    for (int d = tid; d < DIMV; d += 256) {
        float v = g_h[(size_t)row * DIMV + d];
        sh[d] = v; s += v;
    }
#pragma unroll
    for (int o = 16; o; o >>= 1) s += __shfl_xor_sync(0xffffffffu, s, o);
    if (lane == 0) sbuf[w] = s;
    __syncthreads();
    if (w == 0) {
        float t = (lane < 8) ? sbuf[lane] : 0.f;
#pragma unroll
        for (int o = 4; o; o >>= 1) t += __shfl_xor_sync(0xffffffffu, t, o);
        if (lane == 0) sbuf[0] = t;
    }
    __syncthreads();
    float mu = sbuf[0] * (1.f / DIMV);
    __syncthreads();

    float s2 = 0.f;
    for (int d = tid; d < DIMV; d += 256) {
        float dv = sh[d] - mu;
        s2 += dv * dv;
    }
#pragma unroll
    for (int o = 16; o; o >>= 1) s2 += __shfl_xor_sync(0xffffffffu, s2, o);
    if (lane == 0) sbuf[w] = s2;
    __syncthreads();
    if (w == 0) {
        float t = (lane < 8) ? sbuf[lane] : 0.f;
#pragma unroll
        for (int o = 4; o; o >>= 1) t += __shfl_xor_sync(0xffffffffu, t, o);
        if (lane == 0) sbuf[0] = t;
    }
    __syncthreads();
    float var = sbuf[0] * (1.f / DIMV);
    float inv = rsqrtf(var + 1e-5f);
    for (int d = tid; d < DIMV; d += 256) {
        out[(size_t)row * DIMV + d] = (sh[d] - mu) * inv * nw[d] + nb[d];
    }
}

// ---------------- host orchestration ---------------------------------------

extern "C" void kernel_launch(void* const* d_in, const int* in_sizes, int n_in,
                              void* d_out, int out_size)
{
    const float* x       = (const float*)d_in[0];
    const float* patch_w = (const float*)d_in[1];
    const float* patch_b = (const float*)d_in[2];
    const float* pos     = (const float*)d_in[3];
    const float* in_w    = (const float*)d_in[4];
    const float* conv_w  = (const float*)d_in[5];
    const float* conv_b  = (const float*)d_in[6];
    const float* xpw     = (const float*)d_in[7];
    const float* dtw     = (const float*)d_in[8];
    const float* dtb     = (const float*)d_in[9];
    const float* alog    = (const float*)d_in[10];
    const float* Dp      = (const float*)d_in[11];
    const float* ow      = (const float*)d_in[12];
    const float* kbw     = (const float*)d_in[13];
    const float* kco     = (const float*)d_in[14];
    const float* kbi     = (const float*)d_in[15];
    const float* nw      = (const float*)d_in[16];
    const float* nb      = (const float*)d_in[17];
    float* out = (float*)d_out;

    cudaFuncSetAttribute(tgemm<false, false, false>, cudaFuncAttributeMaxDynamicSharedMemorySize, SMEMT);
    cudaFuncSetAttribute(tgemm<false, false, true >, cudaFuncAttributeMaxDynamicSharedMemorySize, SMEMT);
    cudaFuncSetAttribute(tgemm<true,  false, false>, cudaFuncAttributeMaxDynamicSharedMemorySize, SMEMT);
    cudaFuncSetAttribute(tgemm<false, true,  false>, cudaFuncAttributeMaxDynamicSharedMemorySize, SMEMT);

    float *p_tmp, *p_h, *p_hr, *p_xr, *p_x1, *p_yg, *p_basis, *p_wkan;
    float *p_wi, *p_wo, *p_wp, *p_wkb;
    cudaGetSymbolAddress((void**)&p_tmp,   g_tmp);
    cudaGetSymbolAddress((void**)&p_h,     g_h);
    cudaGetSymbolAddress((void**)&p_hr,    g_hr);
    cudaGetSymbolAddress((void**)&p_xr,    g_xr);
    cudaGetSymbolAddress((void**)&p_x1,    g_x1);
    cudaGetSymbolAddress((void**)&p_yg,    g_yg);
    cudaGetSymbolAddress((void**)&p_basis, g_basis);
    cudaGetSymbolAddress((void**)&p_wkan,  g_wkan);
    cudaGetSymbolAddress((void**)&p_wi,    g_wi);
    cudaGetSymbolAddress((void**)&p_wo,    g_wo);
    cudaGetSymbolAddress((void**)&p_wp,    g_wp);
    cudaGetSymbolAddress((void**)&p_wkb,   g_wkb);

    const int T = 256;
    const int MB = TOKV / 128;   // 64
    const int EW4 = (TOKV * DIMV / 4 + T - 1) / T;      // h-sized f4 grids
    const int EX4 = (TOKV * DIV / 4 + T - 1) / T;       // x1-sized f4 grids

    // ---- weight tf32 rounding ----
    {
        int n4;
        n4 = NLV * 2 * DIV * DIMV / 4;
        round4_k<<<(n4 + T - 1) / T, T>>>(in_w, p_wi, n4);
        n4 = NLV * DIMV * DIV / 4;
        round4_k<<<(n4 + T - 1) / T, T>>>(ow, p_wo, n4);
        n4 = DIMV * DIMV / 4;
        round4_k<<<(n4 + T - 1) / T, T>>>(patch_w, p_wp, n4);
        n4 = 4 * DIMV * DIMV / 4;
        round4_k<<<(n4 + T - 1) / T, T>>>(kbw, p_wkb, n4);
    }

    // ---- patch embed ----
    im2col_k<<<EW4, T>>>(x);
    tgemm<true, false, false><<<dim3(DIMV / 128, MB), T, SMEMT>>>(
        p_tmp, p_wp, patch_b, p_h, nullptr, TOKV, DIMV, DIMV);
    addpos_k<<<EW4, T>>>(pos);

    for (int i = 0; i < NLV; i++) {
        tgemm<false, false, false><<<dim3(2 * DIV / 128, MB), T, SMEMT>>>(
            p_hr, p_wi + (size_t)i * 2 * DIV * DIMV, nullptr, p_xr, nullptr,
            TOKV, 2 * DIV, DIMV);
        conv_silu_k<<<EX4, T>>>(
            conv_w + (size_t)i * DIV * 4, conv_b + (size_t)i * DIV);
        dtbp_k<<<TOKV / 64, T>>>(
            dtw + (size_t)i * DSV * DIV, dtb + (size_t)i * DSV,
            xpw + (size_t)i * 2 * DSV * DIV, alog + (size_t)i * DSV);
        scan_k<<<64, 256>>>();
        yg_k<<<EX4, T>>>(Dp + (size_t)i * DIV);
        tgemm<false, false, true><<<dim3(DIMV / 128, MB), T, SMEMT>>>(
            p_yg, p_wo + (size_t)i * DIMV * DIV, nullptr, p_h, p_hr,
            TOKV, DIMV, DIV);

        if (i % 3 == 2) {
            int j = i / 3;
            repack_k<<<(DIMV * KANK + T - 1) / T, T>>>(
                kco + (size_t)j * DIMV * DIMV * 8);
            basis_k<<<EW4, T>>>();
            tgemm<true, false, false><<<dim3(DIMV / 128, MB), T, SMEMT>>>(
                p_hr, p_wkb + (size_t)j * DIMV * DIMV, kbi + (size_t)j * DIMV,
                p_tmp, nullptr, TOKV, DIMV, DIMV);
            tgemm<false, true, false><<<dim3(DIMV / 128, MB), T, SMEMT>>>(
                p_basis, p_wkan, nullptr, p_tmp, nullptr,
                TOKV, DIMV, KANK);
            resadd_k<<<EW4, T>>>();
        }
    }

    ln_k<<<TOKV, 256>>>(nw, nb, out);
}